// round 10
// baseline (speedup 1.0000x reference)
#include <cuda_runtime.h>
#include <cuda_fp16.h>
#include <math.h>
#include <stdint.h>

// ---------------- constants ----------------
#define BATCH   2
#define SEQ     4096
#define ROWS    (BATCH*SEQ)        // 8192
#define DMODEL  2048
#define DSTATE  64
#define DHEAD   64
#define NHEADS  32
#define CHUNK   64
#define NCHUNK  (SEQ/CHUNK)        // 64
#define CONVD   6144
#define ZXB_LD  8192               // cols we compute of zxbcdt (dt cols unused)
#define RMS_EPS 1.1920929e-07f

// ---------------- scratch ----------------
__device__ float  g_zxbc[(size_t)ROWS * ZXB_LD];
__device__ float  g_xbca[(size_t)ROWS * CONVD];   // only C region (cols 4096..6143) used now
__device__ float  g_y   [(size_t)ROWS * DMODEL];
__device__ __half g_yn  [(size_t)ROWS * DMODEL];
__device__ float  g_cs  [(size_t)BATCH*NHEADS*NCHUNK*DSTATE];
__device__ float  g_prev[(size_t)BATCH*NHEADS*NCHUNK*DSTATE];
__device__ __half g_ut  [(size_t)ROWS * DMODEL];
__device__ __half g_wit [(size_t)ZXB_LD * DMODEL];
__device__ __half g_wot [(size_t)DMODEL * DMODEL];

// ---------------- helpers ----------------
__device__ __forceinline__ void cp16(void* dst, const void* src) {
    unsigned saddr = (unsigned)__cvta_generic_to_shared(dst);
    asm volatile("cp.async.cg.shared.global [%0], [%1], 16;" :: "r"(saddr), "l"(src));
}
__device__ __forceinline__ float silu(float v) { return v / (1.f + expf(-v)); }

__global__ void h_convert(const float* __restrict__ in, __half* __restrict__ out, size_t n4)
{
    size_t i = (size_t)blockIdx.x * blockDim.x + threadIdx.x;
    if (i >= n4) return;
    float4 v = ((const float4*)in)[i];
    __half2 lo = __floats2half2_rn(v.x, v.y);
    __half2 hi = __floats2half2_rn(v.z, v.w);
    uint2 o;
    o.x = *(unsigned*)&lo;
    o.y = *(unsigned*)&hi;
    ((uint2*)out)[i] = o;
}

// ============================================================================
// GEMM: C[M,N] = A[M,K] * B[N,K]^T ; fp16 in, fp32 accumulate.
// Block 128x256, warp tile 64x64 (8 warps, 2m x 4n), K-tile 64 halfs,
// SW128 swizzle, m16n8k16. 3-stage cp.async ring (48KB/stage), ONE sync
// per K-tile, 1 CTA/SM. 8 ldmatrix.x4 feed 32 MMAs per k-step.
// ============================================================================
#define NSTG  3
#define KT    64
#define ASZ   (128 * 32)            // u32: A stage (128 rows x 128B)
#define BSZ   (256 * 32)            // u32: B stage (256 rows x 128B)
#define STG   (ASZ + BSZ)           // 12288 u32 = 48KB
#define GSMEM (NSTG * STG * 4)      // 147456 B

__global__ __launch_bounds__(256, 1) void gemm_tn_f16(
    const __half* __restrict__ A, const __half* __restrict__ B,
    float* __restrict__ C, int M, int N, int K)
{
    extern __shared__ __align__(16) unsigned sm[];

    const int tid  = threadIdx.x;
    const int row0 = blockIdx.y * 128;
    const int col0 = blockIdx.x * 256;
    const int warp = tid >> 5, lane = tid & 31;
    const int wm = warp >> 2, wn = warp & 3;

    float acc[4][8][4];
#pragma unroll
    for (int i = 0; i < 4; i++)
#pragma unroll
        for (int j = 0; j < 8; j++)
#pragma unroll
            for (int k = 0; k < 4; k++) acc[i][j][k] = 0.f;

    const __half* Ag = A + (size_t)row0 * K;
    const __half* Bg = B + (size_t)col0 * K;
    const int NT = K / KT;

    auto issue = [&](int j) {
        unsigned* as = sm + (j % NSTG) * STG;
        unsigned* bs = as + ASZ;
        int k0 = j * KT;
#pragma unroll
        for (int i = 0; i < 4; i++) {          // A: 1024 16B chunks
            int ch = tid + i * 256;
            int r = ch >> 3, c = ch & 7;
            cp16(&as[r * 32 + ((c ^ (r & 7)) << 2)], Ag + (size_t)r * K + k0 + c * 8);
        }
#pragma unroll
        for (int i = 0; i < 8; i++) {          // B: 2048 16B chunks
            int ch = tid + i * 256;
            int r = ch >> 3, c = ch & 7;
            cp16(&bs[r * 32 + ((c ^ (r & 7)) << 2)], Bg + (size_t)r * K + k0 + c * 8);
        }
        asm volatile("cp.async.commit_group;");
    };

    issue(0);
    if (NT > 1) issue(1);

    const unsigned smb = (unsigned)__cvta_generic_to_shared(sm);
    const int arow = wm * 64 + (lane & 15);            // + mt*16
    const int acs  = lane >> 4;
    const int brow = wn * 64 + ((lane >> 4) << 3) + (lane & 7);  // + p*16
    const int bcs  = (lane >> 3) & 1;

    for (int t = 0; t < NT; t++) {
        if (t + 1 < NT) {
            asm volatile("cp.async.wait_group 1;");
        } else {
            asm volatile("cp.async.wait_group 0;");
        }
        __syncthreads();
        if (t + 2 < NT) issue(t + 2);

        const unsigned sb = smb + (unsigned)(t % NSTG) * (STG * 4);

#pragma unroll
        for (int ks = 0; ks < 4; ks++) {
            unsigned a[4][4], bf[8][2];
#pragma unroll
            for (int mt = 0; mt < 4; mt++) {
                int r = arow + mt * 16;
                unsigned ad = sb + (unsigned)(r * 128 + (((2 * ks + acs) ^ (r & 7)) << 4));
                asm volatile(
                    "ldmatrix.sync.aligned.m8n8.x4.shared.b16 {%0,%1,%2,%3}, [%4];"
                    : "=r"(a[mt][0]), "=r"(a[mt][1]), "=r"(a[mt][2]), "=r"(a[mt][3])
                    : "r"(ad));
            }
#pragma unroll
            for (int p = 0; p < 4; p++) {
                int r = brow + p * 16;
                unsigned bd = sb + (unsigned)(ASZ * 4) +
                              (unsigned)(r * 128 + (((2 * ks + bcs) ^ (r & 7)) << 4));
                asm volatile(
                    "ldmatrix.sync.aligned.m8n8.x4.shared.b16 {%0,%1,%2,%3}, [%4];"
                    : "=r"(bf[2 * p][0]), "=r"(bf[2 * p][1]),
                      "=r"(bf[2 * p + 1][0]), "=r"(bf[2 * p + 1][1])
                    : "r"(bd));
            }
#pragma unroll
            for (int mt = 0; mt < 4; mt++)
#pragma unroll
                for (int nt = 0; nt < 8; nt++)
                    asm volatile(
                        "mma.sync.aligned.m16n8k16.row.col.f32.f16.f16.f32 "
                        "{%0,%1,%2,%3}, {%4,%5,%6,%7}, {%8,%9}, {%0,%1,%2,%3};"
                        : "+f"(acc[mt][nt][0]), "+f"(acc[mt][nt][1]),
                          "+f"(acc[mt][nt][2]), "+f"(acc[mt][nt][3])
                        : "r"(a[mt][0]), "r"(a[mt][1]), "r"(a[mt][2]), "r"(a[mt][3]),
                          "r"(bf[nt][0]), "r"(bf[nt][1]));
        }
    }

    const int gg = lane >> 2, tt = lane & 3;
#pragma unroll
    for (int mt = 0; mt < 4; mt++) {
        int r = row0 + wm * 64 + mt * 16 + gg;
#pragma unroll
        for (int nt = 0; nt < 8; nt++) {
            int cc = col0 + wn * 64 + nt * 8 + 2 * tt;
            *(float2*)&C[(size_t)r * N + cc]       = make_float2(acc[mt][nt][0], acc[mt][nt][1]);
            *(float2*)&C[(size_t)(r + 8) * N + cc] = make_float2(acc[mt][nt][2], acc[mt][nt][3]);
        }
    }
}

// ============================================================================
// Fused conv+SiLU+SSD. Each block (b,h,c) convolves its own x/B/C 64x64
// tiles from zxbc (halo rows +-1), writes C tile to xbca (for combine),
// then computes G, Y_diag, chunk state. Conv math identical to the old
// standalone kernel (same fmaf chain, same silu).
// ============================================================================
#define SPAD 68
#define TSZ  (64 * SPAD)
#define SSD_SMEM (4 * TSZ * 4)     // Xs, Bs, Cs, Gs = 69632 B

__global__ __launch_bounds__(256, 2) void ssd_chunk_kernel(
    const float* __restrict__ zxbc, const float* __restrict__ cw,
    const float* __restrict__ cb,   float* __restrict__ xbca,
    float* __restrict__ ydiag,      float* __restrict__ cs)
{
    extern __shared__ float ssm[];
    float* Xs = ssm;
    float* Bs = ssm + TSZ;
    float* Cs = ssm + 2 * TSZ;
    float* Gs = ssm + 3 * TSZ;

    int bid = blockIdx.x;
    int c  = bid & 63;
    int bh = bid >> 6;
    int h  = bh & 31;
    int b  = bh >> 5;
    int sl0 = c * CHUNK;
    size_t rbase = (size_t)b * SEQ + sl0;
    int tid = threadIdx.x;

    // ---- load + conv + silu for the 3 regions ----
#pragma unroll
    for (int reg = 0; reg < 3; reg++) {
        float* dst = (reg == 0) ? Xs : (reg == 1) ? Bs : Cs;
        int chbase = reg * 2048 + h * 64;
        for (int i = tid; i < 64 * 16; i += 256) {
            int l = i >> 4, q = (i & 15) * 4;
            size_t r = rbase + l;
            int sl = sl0 + l;
            const float* p = zxbc + r * ZXB_LD + DMODEL + chbase + q;
            float4 x0 = *(const float4*)p;
            float4 xm = (sl > 0)       ? *(const float4*)(p - ZXB_LD) : make_float4(0.f,0.f,0.f,0.f);
            float4 xp = (sl < SEQ - 1) ? *(const float4*)(p + ZXB_LD) : make_float4(0.f,0.f,0.f,0.f);
            int ch = chbase + q;
            float4 v;
            v.x = fmaf(cw[3*ch+0], xm.x, fmaf(cw[3*ch+1], x0.x, fmaf(cw[3*ch+2], xp.x, cb[ch])));
            v.y = fmaf(cw[3*ch+3], xm.y, fmaf(cw[3*ch+4], x0.y, fmaf(cw[3*ch+5], xp.y, cb[ch+1])));
            v.z = fmaf(cw[3*ch+6], xm.z, fmaf(cw[3*ch+7], x0.z, fmaf(cw[3*ch+8], xp.z, cb[ch+2])));
            v.w = fmaf(cw[3*ch+9], xm.w, fmaf(cw[3*ch+10], x0.w, fmaf(cw[3*ch+11], xp.w, cb[ch+3])));
            v.x = silu(v.x); v.y = silu(v.y); v.z = silu(v.z); v.w = silu(v.w);
            *(float4*)&dst[l * SPAD + q] = v;
            if (reg == 2)   // combine needs silu(conv(C)) -- same layout as before
                *(float4*)&xbca[r * CONVD + 2 * DMODEL + h * 64 + q] = v;
        }
    }
    for (int i = tid; i < TSZ; i += 256) Gs[i] = 0.f;
    __syncthreads();

    // ---- G[l][m] = C[l] . B[m], lower triangle ----
    {
        const int l  = tid >> 2;
        const int m0 = tid & 3;
        for (int m = m0; m <= l; m += 4) {
            float4 s = make_float4(0.f, 0.f, 0.f, 0.f);
#pragma unroll 4
            for (int n = 0; n < 64; n += 4) {
                float4 cv = *(const float4*)&Cs[l * SPAD + n];
                float4 bv = *(const float4*)&Bs[m * SPAD + n];
                s.x = fmaf(cv.x, bv.x, s.x);
                s.y = fmaf(cv.y, bv.y, s.y);
                s.z = fmaf(cv.z, bv.z, s.z);
                s.w = fmaf(cv.w, bv.w, s.w);
            }
            Gs[l * SPAD + m] = (s.x + s.y) + (s.z + s.w);
        }
    }
    __syncthreads();

    // ---- Y[l][p] = sum_m G[l][m] x[m][p] ; 2 rows x 8 cols per thread ----
    {
        const int lt = tid & 31;          // rows lt, lt+32
        const int qt = tid >> 5;          // col block qt*8
        float4 a00 = make_float4(0.f,0.f,0.f,0.f), a01 = a00;
        float4 a10 = a00, a11 = a00;
        const float* gr0 = &Gs[lt * SPAD];
        const float* gr1 = &Gs[(lt + 32) * SPAD];
#pragma unroll 4
        for (int m = 0; m < 64; m++) {
            const float* xr = &Xs[m * SPAD + qt * 8];
            float4 x0 = *(const float4*)&xr[0];
            float4 x1 = *(const float4*)&xr[4];
            float g0 = gr0[m], g1 = gr1[m];
            a00.x = fmaf(g0, x0.x, a00.x); a00.y = fmaf(g0, x0.y, a00.y);
            a00.z = fmaf(g0, x0.z, a00.z); a00.w = fmaf(g0, x0.w, a00.w);
            a01.x = fmaf(g0, x1.x, a01.x); a01.y = fmaf(g0, x1.y, a01.y);
            a01.z = fmaf(g0, x1.z, a01.z); a01.w = fmaf(g0, x1.w, a01.w);
            a10.x = fmaf(g1, x0.x, a10.x); a10.y = fmaf(g1, x0.y, a10.y);
            a10.z = fmaf(g1, x0.z, a10.z); a10.w = fmaf(g1, x0.w, a10.w);
            a11.x = fmaf(g1, x1.x, a11.x); a11.y = fmaf(g1, x1.y, a11.y);
            a11.z = fmaf(g1, x1.z, a11.z); a11.w = fmaf(g1, x1.w, a11.w);
        }
        float* yr0 = &ydiag[(rbase + lt) * DMODEL + h * 64 + qt * 8];
        float* yr1 = &ydiag[(rbase + lt + 32) * DMODEL + h * 64 + qt * 8];
        *(float4*)&yr0[0] = a00;
        *(float4*)&yr0[4] = a01;
        *(float4*)&yr1[0] = a10;
        *(float4*)&yr1[4] = a11;
    }

    // ---- chunk state ----
    if (tid < 64) {
        float a = 0.f;
#pragma unroll 8
        for (int ll = 0; ll < 64; ll++)
            a = fmaf(Xs[ll * SPAD + tid], Bs[ll * SPAD + tid], a);
        cs[(size_t)bid * 64 + tid] = a;
    }
}

// ============================================================================
// Inter-chunk scan (constant decay exp(63*A_log[h]) per head)
// ============================================================================
__global__ void scan_kernel(const float* __restrict__ cs, const float* __restrict__ A_log,
                            float* __restrict__ prev)
{
    int bh = blockIdx.x;
    int h  = bh & 31;
    int n  = threadIdx.x;
    float d = expf(63.f * A_log[h]);
    float s = 0.f;
    for (int c = 0; c < NCHUNK; c++) {
        size_t idx = ((size_t)bh * NCHUNK + c) * 64 + n;
        prev[idx] = s;
        s = s * d + cs[idx];
    }
}

// ============================================================================
// Y = Y_diag + Y_off; gate with silu(z); RMSNorm. Output fp16.
// ============================================================================
__global__ __launch_bounds__(256) void combine_kernel(
    const float* __restrict__ ydiag, const float* __restrict__ zxbc,
    const float* __restrict__ xbca,  const float* __restrict__ prev,
    const float* __restrict__ rms_w, __half* __restrict__ yn)
{
    int r = blockIdx.x;
    int b = r >> 12;
    int l = r & (SEQ - 1);
    int c = l >> 6;

    __shared__ float sh_yoff[NHEADS];
    __shared__ float sh_red[8];

    int tid = threadIdx.x, warp = tid >> 5, lane = tid & 31;

    for (int h = warp; h < NHEADS; h += 8) {
        const float* Crow = xbca + (size_t)r * CONVD + 2 * DMODEL + h * 64;
        const float* pv   = prev + ((size_t)(b * NHEADS + h) * NCHUNK + c) * 64;
        int n0 = lane * 2;
        float v = Crow[n0] * pv[n0] + Crow[n0 + 1] * pv[n0 + 1];
#pragma unroll
        for (int o = 16; o; o >>= 1) v += __shfl_down_sync(0xffffffffu, v, o);
        if (lane == 0) sh_yoff[h] = v;
    }
    __syncthreads();

    float vals[8];
    float ss = 0.f;
#pragma unroll
    for (int j = 0; j < 8; j++) {
        int d = tid + j * 256;
        float z  = zxbc[(size_t)r * ZXB_LD + d];
        float sz = z / (1.f + expf(-z));
        float y  = (ydiag[(size_t)r * DMODEL + d] + sh_yoff[d >> 6]) * sz;
        vals[j] = y;
        ss += y * y;
    }
#pragma unroll
    for (int o = 16; o; o >>= 1) ss += __shfl_down_sync(0xffffffffu, ss, o);
    if (lane == 0) sh_red[warp] = ss;
    __syncthreads();
    if (tid == 0) {
        float t = 0.f;
#pragma unroll
        for (int w = 0; w < 8; w++) t += sh_red[w];
        sh_red[0] = rsqrtf(t / (float)DMODEL + RMS_EPS);
    }
    __syncthreads();
    float scale = sh_red[0];
#pragma unroll
    for (int j = 0; j < 8; j++) {
        int d = tid + j * 256;
        yn[(size_t)r * DMODEL + d] = __float2half_rn(vals[j] * scale * rms_w[d]);
    }
}

// ============================================================================
// launch
// ============================================================================
extern "C" void kernel_launch(void* const* d_in, const int* in_sizes, int n_in,
                              void* d_out, int out_size)
{
    const float* u      = (const float*)d_in[0];
    const float* W_in   = (const float*)d_in[1];
    const float* W_out  = (const float*)d_in[2];
    const float* conv_w = (const float*)d_in[3];
    const float* conv_b = (const float*)d_in[4];
    const float* A_log  = (const float*)d_in[5];
    const float* rms_w  = (const float*)d_in[6];
    float* out = (float*)d_out;

    float *zxbc, *xbca, *y, *cs, *prev;
    __half *yn, *ut, *wit, *wot;
    cudaGetSymbolAddress((void**)&zxbc, g_zxbc);
    cudaGetSymbolAddress((void**)&xbca, g_xbca);
    cudaGetSymbolAddress((void**)&y,    g_y);
    cudaGetSymbolAddress((void**)&yn,   g_yn);
    cudaGetSymbolAddress((void**)&cs,   g_cs);
    cudaGetSymbolAddress((void**)&prev, g_prev);
    cudaGetSymbolAddress((void**)&ut,   g_ut);
    cudaGetSymbolAddress((void**)&wit,  g_wit);
    cudaGetSymbolAddress((void**)&wot,  g_wot);

    static bool attr_done = false;
    if (!attr_done) {
        cudaFuncSetAttribute(gemm_tn_f16, cudaFuncAttributeMaxDynamicSharedMemorySize, GSMEM);
        cudaFuncSetAttribute(ssd_chunk_kernel, cudaFuncAttributeMaxDynamicSharedMemorySize, SSD_SMEM);
        attr_done = true;
    }

    // 0) convert operands to fp16
    {
        size_t n4u = (size_t)ROWS * DMODEL / 4;
        h_convert<<<(unsigned)((n4u + 255) / 256), 256>>>(u, ut, n4u);
        size_t n4w = (size_t)ZXB_LD * DMODEL / 4;
        h_convert<<<(unsigned)((n4w + 255) / 256), 256>>>(W_in, wit, n4w);
        size_t n4o = (size_t)DMODEL * DMODEL / 4;
        h_convert<<<(unsigned)((n4o + 255) / 256), 256>>>(W_out, wot, n4o);
    }
    // 1) zxbc = u @ W_in^T (first 8192 output cols; dt cols unused)
    gemm_tn_f16<<<dim3(ZXB_LD / 256, ROWS / 128), 256, GSMEM>>>(ut, wit, zxbc, ROWS, ZXB_LD, DMODEL);
    // 2) fused conv + silu + per-chunk SSD
    ssd_chunk_kernel<<<BATCH * NHEADS * NCHUNK, 256, SSD_SMEM>>>(zxbc, conv_w, conv_b, xbca, y, cs);
    // 3) inter-chunk scan
    scan_kernel<<<BATCH * NHEADS, 64>>>(cs, A_log, prev);
    // 4) Y_off + gate + rmsnorm (writes fp16)
    combine_kernel<<<ROWS, 256>>>(y, zxbc, xbca, prev, rms_w, yn);
    // 5) out = yn @ W_out^T
    gemm_tn_f16<<<dim3(DMODEL / 256, ROWS / 128), 256, GSMEM>>>(yn, wot, out, ROWS, DMODEL, DMODEL);
}

// round 11
// speedup vs baseline: 1.1042x; 1.1042x over previous
#include <cuda_runtime.h>
#include <cuda_fp16.h>
#include <math.h>
#include <stdint.h>

// ---------------- constants ----------------
#define BATCH   2
#define SEQ     4096
#define ROWS    (BATCH*SEQ)        // 8192
#define DMODEL  2048
#define DSTATE  64
#define DHEAD   64
#define NHEADS  32
#define CHUNK   64
#define NCHUNK  (SEQ/CHUNK)        // 64
#define CONVD   6144
#define ZXB_LD  8192               // cols we compute of zxbcdt (dt cols unused)
#define RMS_EPS 1.1920929e-07f

// ---------------- scratch ----------------
__device__ float  g_zxbc[(size_t)ROWS * ZXB_LD];
__device__ float  g_xbca[(size_t)ROWS * CONVD];   // only C region (cols 4096..6143) used
__device__ float  g_y   [(size_t)ROWS * DMODEL];
__device__ __half g_yn  [(size_t)ROWS * DMODEL];
__device__ float  g_cs  [(size_t)BATCH*NHEADS*NCHUNK*DSTATE];
__device__ float  g_prev[(size_t)BATCH*NHEADS*NCHUNK*DSTATE];
__device__ __half g_ut  [(size_t)ROWS * DMODEL];
__device__ __half g_wit [(size_t)ZXB_LD * DMODEL];
__device__ __half g_wot [(size_t)DMODEL * DMODEL];

// ---------------- helpers ----------------
__device__ __forceinline__ void cp16(void* dst, const void* src) {
    unsigned saddr = (unsigned)__cvta_generic_to_shared(dst);
    asm volatile("cp.async.cg.shared.global [%0], [%1], 16;" :: "r"(saddr), "l"(src));
}
__device__ __forceinline__ float silu(float v) { return v / (1.f + expf(-v)); }

__global__ void h_convert(const float* __restrict__ in, __half* __restrict__ out, size_t n4)
{
    size_t i = (size_t)blockIdx.x * blockDim.x + threadIdx.x;
    if (i >= n4) return;
    float4 v = ((const float4*)in)[i];
    __half2 lo = __floats2half2_rn(v.x, v.y);
    __half2 hi = __floats2half2_rn(v.z, v.w);
    uint2 o;
    o.x = *(unsigned*)&lo;
    o.y = *(unsigned*)&hi;
    ((uint2*)out)[i] = o;
}

// ============================================================================
// GEMM (R9 config): C[M,N] = A[M,K] * B[N,K]^T ; fp16 in, fp32 accumulate.
// Block 128x128, warp tile 64x32 (8 warps 2x4), K-tile 64 halfs, SW128
// swizzle, m16n8k16. 3-stage cp.async ring, ONE sync per K-tile, 96KB smem
// -> 2 CTAs/SM (bubble coverage).
// ============================================================================
#define NSTG  3
#define KT    64
#define ASZ   (128 * 32)            // u32 per stage per matrix (128 rows x 128B)
#define STG   (2 * ASZ)             // 32KB per stage
#define GSMEM (NSTG * STG * 4)      // 98304 B

__global__ __launch_bounds__(256, 2) void gemm_tn_f16(
    const __half* __restrict__ A, const __half* __restrict__ B,
    float* __restrict__ C, int M, int N, int K)
{
    extern __shared__ __align__(16) unsigned sm[];

    const int tid  = threadIdx.x;
    const int row0 = blockIdx.y * 128;
    const int col0 = blockIdx.x * 128;
    const int warp = tid >> 5, lane = tid & 31;
    const int wm = warp >> 2, wn = warp & 3;

    float acc[4][4][4];
#pragma unroll
    for (int i = 0; i < 4; i++)
#pragma unroll
        for (int j = 0; j < 4; j++)
#pragma unroll
            for (int k = 0; k < 4; k++) acc[i][j][k] = 0.f;

    const __half* Ag = A + (size_t)row0 * K;
    const __half* Bg = B + (size_t)col0 * K;
    const int NT = K / KT;

    auto issue = [&](int j) {
        unsigned* as = sm + (j % NSTG) * STG;
        unsigned* bs = as + ASZ;
        int k0 = j * KT;
#pragma unroll
        for (int i = 0; i < 4; i++) {
            int ch = tid + i * 256;
            int r = ch >> 3, c = ch & 7;
            cp16(&as[r * 32 + ((c ^ (r & 7)) << 2)], Ag + (size_t)r * K + k0 + c * 8);
        }
#pragma unroll
        for (int i = 0; i < 4; i++) {
            int ch = tid + i * 256;
            int r = ch >> 3, c = ch & 7;
            cp16(&bs[r * 32 + ((c ^ (r & 7)) << 2)], Bg + (size_t)r * K + k0 + c * 8);
        }
        asm volatile("cp.async.commit_group;");
    };

    issue(0);
    if (NT > 1) issue(1);

    const unsigned smb = (unsigned)__cvta_generic_to_shared(sm);
    const int arow = wm * 64 + (lane & 15);    // + mt*16
    const int acs  = lane >> 4;
    const int brow = wn * 32 + (lane & 7);     // + nt*8
    const int bcs  = (lane >> 3) & 1;

    for (int t = 0; t < NT; t++) {
        if (t + 1 < NT) {
            asm volatile("cp.async.wait_group 1;");
        } else {
            asm volatile("cp.async.wait_group 0;");
        }
        __syncthreads();
        if (t + 2 < NT) issue(t + 2);

        const unsigned sb = smb + (unsigned)(t % NSTG) * (STG * 4);

#pragma unroll
        for (int ks = 0; ks < 4; ks++) {
            unsigned a[4][4], bf[4][2];
#pragma unroll
            for (int mt = 0; mt < 4; mt++) {
                int r = arow + mt * 16;
                unsigned ad = sb + (unsigned)(r * 128 + (((2 * ks + acs) ^ (r & 7)) << 4));
                asm volatile(
                    "ldmatrix.sync.aligned.m8n8.x4.shared.b16 {%0,%1,%2,%3}, [%4];"
                    : "=r"(a[mt][0]), "=r"(a[mt][1]), "=r"(a[mt][2]), "=r"(a[mt][3])
                    : "r"(ad));
            }
#pragma unroll
            for (int nt = 0; nt < 4; nt++) {
                int r = brow + nt * 8;
                unsigned bd = sb + (unsigned)(ASZ * 4) +
                              (unsigned)(r * 128 + (((2 * ks + bcs) ^ (r & 7)) << 4));
                asm volatile(
                    "ldmatrix.sync.aligned.m8n8.x2.shared.b16 {%0,%1}, [%2];"
                    : "=r"(bf[nt][0]), "=r"(bf[nt][1])
                    : "r"(bd));
            }
#pragma unroll
            for (int mt = 0; mt < 4; mt++)
#pragma unroll
                for (int nt = 0; nt < 4; nt++)
                    asm volatile(
                        "mma.sync.aligned.m16n8k16.row.col.f32.f16.f16.f32 "
                        "{%0,%1,%2,%3}, {%4,%5,%6,%7}, {%8,%9}, {%0,%1,%2,%3};"
                        : "+f"(acc[mt][nt][0]), "+f"(acc[mt][nt][1]),
                          "+f"(acc[mt][nt][2]), "+f"(acc[mt][nt][3])
                        : "r"(a[mt][0]), "r"(a[mt][1]), "r"(a[mt][2]), "r"(a[mt][3]),
                          "r"(bf[nt][0]), "r"(bf[nt][1]));
        }
    }

    const int gg = lane >> 2, tt = lane & 3;
#pragma unroll
    for (int mt = 0; mt < 4; mt++) {
        int r = row0 + wm * 64 + mt * 16 + gg;
#pragma unroll
        for (int nt = 0; nt < 4; nt++) {
            int cc = col0 + wn * 32 + nt * 8 + 2 * tt;
            *(float2*)&C[(size_t)r * N + cc]       = make_float2(acc[mt][nt][0], acc[mt][nt][1]);
            *(float2*)&C[(size_t)(r + 8) * N + cc] = make_float2(acc[mt][nt][2], acc[mt][nt][3]);
        }
    }
}

// ============================================================================
// Fused conv+SiLU+SSD (R10 version -- the winner). Each block (b,h,c)
// convolves its own x/B/C 64x64 tiles from zxbc (halo +-1 row), writes the
// C tile to xbca for combine, then computes G, Y_diag, chunk state.
// ============================================================================
#define SPAD 68
#define TSZ  (64 * SPAD)
#define SSD_SMEM (4 * TSZ * 4)     // Xs, Bs, Cs, Gs = 69632 B

__global__ __launch_bounds__(256, 2) void ssd_chunk_kernel(
    const float* __restrict__ zxbc, const float* __restrict__ cw,
    const float* __restrict__ cb,   float* __restrict__ xbca,
    float* __restrict__ ydiag,      float* __restrict__ cs)
{
    extern __shared__ float ssm[];
    float* Xs = ssm;
    float* Bs = ssm + TSZ;
    float* Cs = ssm + 2 * TSZ;
    float* Gs = ssm + 3 * TSZ;

    int bid = blockIdx.x;
    int c  = bid & 63;
    int bh = bid >> 6;
    int h  = bh & 31;
    int b  = bh >> 5;
    int sl0 = c * CHUNK;
    size_t rbase = (size_t)b * SEQ + sl0;
    int tid = threadIdx.x;

#pragma unroll
    for (int reg = 0; reg < 3; reg++) {
        float* dst = (reg == 0) ? Xs : (reg == 1) ? Bs : Cs;
        int chbase = reg * 2048 + h * 64;
        for (int i = tid; i < 64 * 16; i += 256) {
            int l = i >> 4, q = (i & 15) * 4;
            size_t r = rbase + l;
            int sl = sl0 + l;
            const float* p = zxbc + r * ZXB_LD + DMODEL + chbase + q;
            float4 x0 = *(const float4*)p;
            float4 xm = (sl > 0)       ? *(const float4*)(p - ZXB_LD) : make_float4(0.f,0.f,0.f,0.f);
            float4 xp = (sl < SEQ - 1) ? *(const float4*)(p + ZXB_LD) : make_float4(0.f,0.f,0.f,0.f);
            int ch = chbase + q;
            float4 v;
            v.x = fmaf(cw[3*ch+0], xm.x, fmaf(cw[3*ch+1], x0.x, fmaf(cw[3*ch+2], xp.x, cb[ch])));
            v.y = fmaf(cw[3*ch+3], xm.y, fmaf(cw[3*ch+4], x0.y, fmaf(cw[3*ch+5], xp.y, cb[ch+1])));
            v.z = fmaf(cw[3*ch+6], xm.z, fmaf(cw[3*ch+7], x0.z, fmaf(cw[3*ch+8], xp.z, cb[ch+2])));
            v.w = fmaf(cw[3*ch+9], xm.w, fmaf(cw[3*ch+10], x0.w, fmaf(cw[3*ch+11], xp.w, cb[ch+3])));
            v.x = silu(v.x); v.y = silu(v.y); v.z = silu(v.z); v.w = silu(v.w);
            *(float4*)&dst[l * SPAD + q] = v;
            if (reg == 2)
                *(float4*)&xbca[r * CONVD + 2 * DMODEL + h * 64 + q] = v;
        }
    }
    for (int i = tid; i < TSZ; i += 256) Gs[i] = 0.f;
    __syncthreads();

    // ---- G[l][m] = C[l] . B[m], lower triangle ----
    {
        const int l  = tid >> 2;
        const int m0 = tid & 3;
        for (int m = m0; m <= l; m += 4) {
            float4 s = make_float4(0.f, 0.f, 0.f, 0.f);
#pragma unroll 4
            for (int n = 0; n < 64; n += 4) {
                float4 cv = *(const float4*)&Cs[l * SPAD + n];
                float4 bv = *(const float4*)&Bs[m * SPAD + n];
                s.x = fmaf(cv.x, bv.x, s.x);
                s.y = fmaf(cv.y, bv.y, s.y);
                s.z = fmaf(cv.z, bv.z, s.z);
                s.w = fmaf(cv.w, bv.w, s.w);
            }
            Gs[l * SPAD + m] = (s.x + s.y) + (s.z + s.w);
        }
    }
    __syncthreads();

    // ---- Y[l][p] = sum_m G[l][m] x[m][p] ; 2 rows x 8 cols per thread ----
    {
        const int lt = tid & 31;
        const int qt = tid >> 5;
        float4 a00 = make_float4(0.f,0.f,0.f,0.f), a01 = a00;
        float4 a10 = a00, a11 = a00;
        const float* gr0 = &Gs[lt * SPAD];
        const float* gr1 = &Gs[(lt + 32) * SPAD];
#pragma unroll 4
        for (int m = 0; m < 64; m++) {
            const float* xr = &Xs[m * SPAD + qt * 8];
            float4 x0 = *(const float4*)&xr[0];
            float4 x1 = *(const float4*)&xr[4];
            float g0 = gr0[m], g1 = gr1[m];
            a00.x = fmaf(g0, x0.x, a00.x); a00.y = fmaf(g0, x0.y, a00.y);
            a00.z = fmaf(g0, x0.z, a00.z); a00.w = fmaf(g0, x0.w, a00.w);
            a01.x = fmaf(g0, x1.x, a01.x); a01.y = fmaf(g0, x1.y, a01.y);
            a01.z = fmaf(g0, x1.z, a01.z); a01.w = fmaf(g0, x1.w, a01.w);
            a10.x = fmaf(g1, x0.x, a10.x); a10.y = fmaf(g1, x0.y, a10.y);
            a10.z = fmaf(g1, x0.z, a10.z); a10.w = fmaf(g1, x0.w, a10.w);
            a11.x = fmaf(g1, x1.x, a11.x); a11.y = fmaf(g1, x1.y, a11.y);
            a11.z = fmaf(g1, x1.z, a11.z); a11.w = fmaf(g1, x1.w, a11.w);
        }
        float* yr0 = &ydiag[(rbase + lt) * DMODEL + h * 64 + qt * 8];
        float* yr1 = &ydiag[(rbase + lt + 32) * DMODEL + h * 64 + qt * 8];
        *(float4*)&yr0[0] = a00;
        *(float4*)&yr0[4] = a01;
        *(float4*)&yr1[0] = a10;
        *(float4*)&yr1[4] = a11;
    }

    // ---- chunk state ----
    if (tid < 64) {
        float a = 0.f;
#pragma unroll 8
        for (int ll = 0; ll < 64; ll++)
            a = fmaf(Xs[ll * SPAD + tid], Bs[ll * SPAD + tid], a);
        cs[(size_t)bid * 64 + tid] = a;
    }
}

// ============================================================================
// Inter-chunk scan (constant decay exp(63*A_log[h]) per head)
// ============================================================================
__global__ void scan_kernel(const float* __restrict__ cs, const float* __restrict__ A_log,
                            float* __restrict__ prev)
{
    int bh = blockIdx.x;
    int h  = bh & 31;
    int n  = threadIdx.x;
    float d = expf(63.f * A_log[h]);
    float s = 0.f;
    for (int c = 0; c < NCHUNK; c++) {
        size_t idx = ((size_t)bh * NCHUNK + c) * 64 + n;
        prev[idx] = s;
        s = s * d + cs[idx];
    }
}

// ============================================================================
// Y = Y_diag + Y_off; gate with silu(z); RMSNorm. Output fp16.
// ============================================================================
__global__ __launch_bounds__(256) void combine_kernel(
    const float* __restrict__ ydiag, const float* __restrict__ zxbc,
    const float* __restrict__ xbca,  const float* __restrict__ prev,
    const float* __restrict__ rms_w, __half* __restrict__ yn)
{
    int r = blockIdx.x;
    int b = r >> 12;
    int l = r & (SEQ - 1);
    int c = l >> 6;

    __shared__ float sh_yoff[NHEADS];
    __shared__ float sh_red[8];

    int tid = threadIdx.x, warp = tid >> 5, lane = tid & 31;

    for (int h = warp; h < NHEADS; h += 8) {
        const float* Crow = xbca + (size_t)r * CONVD + 2 * DMODEL + h * 64;
        const float* pv   = prev + ((size_t)(b * NHEADS + h) * NCHUNK + c) * 64;
        int n0 = lane * 2;
        float v = Crow[n0] * pv[n0] + Crow[n0 + 1] * pv[n0 + 1];
#pragma unroll
        for (int o = 16; o; o >>= 1) v += __shfl_down_sync(0xffffffffu, v, o);
        if (lane == 0) sh_yoff[h] = v;
    }
    __syncthreads();

    float vals[8];
    float ss = 0.f;
#pragma unroll
    for (int j = 0; j < 8; j++) {
        int d = tid + j * 256;
        float z  = zxbc[(size_t)r * ZXB_LD + d];
        float sz = z / (1.f + expf(-z));
        float y  = (ydiag[(size_t)r * DMODEL + d] + sh_yoff[d >> 6]) * sz;
        vals[j] = y;
        ss += y * y;
    }
#pragma unroll
    for (int o = 16; o; o >>= 1) ss += __shfl_down_sync(0xffffffffu, ss, o);
    if (lane == 0) sh_red[warp] = ss;
    __syncthreads();
    if (tid == 0) {
        float t = 0.f;
#pragma unroll
        for (int w = 0; w < 8; w++) t += sh_red[w];
        sh_red[0] = rsqrtf(t / (float)DMODEL + RMS_EPS);
    }
    __syncthreads();
    float scale = sh_red[0];
#pragma unroll
    for (int j = 0; j < 8; j++) {
        int d = tid + j * 256;
        yn[(size_t)r * DMODEL + d] = __float2half_rn(vals[j] * scale * rms_w[d]);
    }
}

// ============================================================================
// launch
// ============================================================================
extern "C" void kernel_launch(void* const* d_in, const int* in_sizes, int n_in,
                              void* d_out, int out_size)
{
    const float* u      = (const float*)d_in[0];
    const float* W_in   = (const float*)d_in[1];
    const float* W_out  = (const float*)d_in[2];
    const float* conv_w = (const float*)d_in[3];
    const float* conv_b = (const float*)d_in[4];
    const float* A_log  = (const float*)d_in[5];
    const float* rms_w  = (const float*)d_in[6];
    float* out = (float*)d_out;

    float *zxbc, *xbca, *y, *cs, *prev;
    __half *yn, *ut, *wit, *wot;
    cudaGetSymbolAddress((void**)&zxbc, g_zxbc);
    cudaGetSymbolAddress((void**)&xbca, g_xbca);
    cudaGetSymbolAddress((void**)&y,    g_y);
    cudaGetSymbolAddress((void**)&yn,   g_yn);
    cudaGetSymbolAddress((void**)&cs,   g_cs);
    cudaGetSymbolAddress((void**)&prev, g_prev);
    cudaGetSymbolAddress((void**)&ut,   g_ut);
    cudaGetSymbolAddress((void**)&wit,  g_wit);
    cudaGetSymbolAddress((void**)&wot,  g_wot);

    static bool attr_done = false;
    if (!attr_done) {
        cudaFuncSetAttribute(gemm_tn_f16, cudaFuncAttributeMaxDynamicSharedMemorySize, GSMEM);
        cudaFuncSetAttribute(ssd_chunk_kernel, cudaFuncAttributeMaxDynamicSharedMemorySize, SSD_SMEM);
        attr_done = true;
    }

    // 0) convert operands to fp16
    {
        size_t n4u = (size_t)ROWS * DMODEL / 4;
        h_convert<<<(unsigned)((n4u + 255) / 256), 256>>>(u, ut, n4u);
        size_t n4w = (size_t)ZXB_LD * DMODEL / 4;
        h_convert<<<(unsigned)((n4w + 255) / 256), 256>>>(W_in, wit, n4w);
        size_t n4o = (size_t)DMODEL * DMODEL / 4;
        h_convert<<<(unsigned)((n4o + 255) / 256), 256>>>(W_out, wot, n4o);
    }
    // 1) zxbc = u @ W_in^T (first 8192 output cols; dt cols unused)
    gemm_tn_f16<<<dim3(ZXB_LD / 128, ROWS / 128), 256, GSMEM>>>(ut, wit, zxbc, ROWS, ZXB_LD, DMODEL);
    // 2) fused conv + silu + per-chunk SSD
    ssd_chunk_kernel<<<BATCH * NHEADS * NCHUNK, 256, SSD_SMEM>>>(zxbc, conv_w, conv_b, xbca, y, cs);
    // 3) inter-chunk scan
    scan_kernel<<<BATCH * NHEADS, 64>>>(cs, A_log, prev);
    // 4) Y_off + gate + rmsnorm (writes fp16)
    combine_kernel<<<ROWS, 256>>>(y, zxbc, xbca, prev, rms_w, yn);
    // 5) out = yn @ W_out^T
    gemm_tn_f16<<<dim3(DMODEL / 128, ROWS / 128), 256, GSMEM>>>(yn, wot, out, ROWS, DMODEL, DMODEL);
}

// round 12
// speedup vs baseline: 1.1847x; 1.0730x over previous
#include <cuda_runtime.h>
#include <cuda_fp16.h>
#include <math.h>
#include <stdint.h>

// ---------------- constants ----------------
#define BATCH   2
#define SEQ     4096
#define ROWS    (BATCH*SEQ)        // 8192
#define DMODEL  2048
#define DSTATE  64
#define DHEAD   64
#define NHEADS  32
#define CHUNK   64
#define NCHUNK  (SEQ/CHUNK)        // 64
#define CONVD   6144
#define ZXB_LD  8192               // cols we compute of zxbcdt (dt cols unused)
#define RMS_EPS 1.1920929e-07f

// ---------------- scratch ----------------
__device__ float  g_zxbc[(size_t)ROWS * ZXB_LD];
__device__ float  g_xbca[(size_t)ROWS * CONVD];   // only C region (cols 4096..6143) used
__device__ float  g_y   [(size_t)ROWS * DMODEL];
__device__ __half g_yn  [(size_t)ROWS * DMODEL];
__device__ float  g_cs  [(size_t)BATCH*NHEADS*NCHUNK*DSTATE];
__device__ float  g_prev[(size_t)BATCH*NHEADS*NCHUNK*DSTATE];
__device__ __half g_ut  [(size_t)ROWS * DMODEL];
__device__ __half g_wit [(size_t)ZXB_LD * DMODEL];
__device__ __half g_wot [(size_t)DMODEL * DMODEL];

// ---------------- helpers ----------------
__device__ __forceinline__ void cp16(void* dst, const void* src) {
    unsigned saddr = (unsigned)__cvta_generic_to_shared(dst);
    asm volatile("cp.async.cg.shared.global [%0], [%1], 16;" :: "r"(saddr), "l"(src));
}
__device__ __forceinline__ float silu(float v) { return v / (1.f + expf(-v)); }

__global__ void h_convert(const float* __restrict__ in, __half* __restrict__ out, size_t n4)
{
    size_t i = (size_t)blockIdx.x * blockDim.x + threadIdx.x;
    if (i >= n4) return;
    float4 v = ((const float4*)in)[i];
    __half2 lo = __floats2half2_rn(v.x, v.y);
    __half2 hi = __floats2half2_rn(v.z, v.w);
    uint2 o;
    o.x = *(unsigned*)&lo;
    o.y = *(unsigned*)&hi;
    ((uint2*)out)[i] = o;
}

// ============================================================================
// GEMM (proven R9/R11 config): C[M,N] = A[M,K] * B[N,K]^T ; fp16 in, fp32 acc.
// Block 128x128, warp tile 64x32 (8 warps 2x4), K-tile 64 halfs, SW128
// swizzle, m16n8k16. 3-stage cp.async ring, ONE sync per K-tile, 2 CTAs/SM.
// ============================================================================
#define NSTG  3
#define KT    64
#define ASZ   (128 * 32)            // u32 per stage per matrix (128 rows x 128B)
#define STG   (2 * ASZ)             // 32KB per stage
#define GSMEM (NSTG * STG * 4)      // 98304 B

__global__ __launch_bounds__(256, 2) void gemm_tn_f16(
    const __half* __restrict__ A, const __half* __restrict__ B,
    float* __restrict__ C, int M, int N, int K)
{
    extern __shared__ __align__(16) unsigned sm[];

    const int tid  = threadIdx.x;
    const int row0 = blockIdx.y * 128;
    const int col0 = blockIdx.x * 128;
    const int warp = tid >> 5, lane = tid & 31;
    const int wm = warp >> 2, wn = warp & 3;

    float acc[4][4][4];
#pragma unroll
    for (int i = 0; i < 4; i++)
#pragma unroll
        for (int j = 0; j < 4; j++)
#pragma unroll
            for (int k = 0; k < 4; k++) acc[i][j][k] = 0.f;

    const __half* Ag = A + (size_t)row0 * K;
    const __half* Bg = B + (size_t)col0 * K;
    const int NT = K / KT;

    auto issue = [&](int j) {
        unsigned* as = sm + (j % NSTG) * STG;
        unsigned* bs = as + ASZ;
        int k0 = j * KT;
#pragma unroll
        for (int i = 0; i < 4; i++) {
            int ch = tid + i * 256;
            int r = ch >> 3, c = ch & 7;
            cp16(&as[r * 32 + ((c ^ (r & 7)) << 2)], Ag + (size_t)r * K + k0 + c * 8);
        }
#pragma unroll
        for (int i = 0; i < 4; i++) {
            int ch = tid + i * 256;
            int r = ch >> 3, c = ch & 7;
            cp16(&bs[r * 32 + ((c ^ (r & 7)) << 2)], Bg + (size_t)r * K + k0 + c * 8);
        }
        asm volatile("cp.async.commit_group;");
    };

    issue(0);
    if (NT > 1) issue(1);

    const unsigned smb = (unsigned)__cvta_generic_to_shared(sm);
    const int arow = wm * 64 + (lane & 15);
    const int acs  = lane >> 4;
    const int brow = wn * 32 + (lane & 7);
    const int bcs  = (lane >> 3) & 1;

    for (int t = 0; t < NT; t++) {
        if (t + 1 < NT) {
            asm volatile("cp.async.wait_group 1;");
        } else {
            asm volatile("cp.async.wait_group 0;");
        }
        __syncthreads();
        if (t + 2 < NT) issue(t + 2);

        const unsigned sb = smb + (unsigned)(t % NSTG) * (STG * 4);

#pragma unroll
        for (int ks = 0; ks < 4; ks++) {
            unsigned a[4][4], bf[4][2];
#pragma unroll
            for (int mt = 0; mt < 4; mt++) {
                int r = arow + mt * 16;
                unsigned ad = sb + (unsigned)(r * 128 + (((2 * ks + acs) ^ (r & 7)) << 4));
                asm volatile(
                    "ldmatrix.sync.aligned.m8n8.x4.shared.b16 {%0,%1,%2,%3}, [%4];"
                    : "=r"(a[mt][0]), "=r"(a[mt][1]), "=r"(a[mt][2]), "=r"(a[mt][3])
                    : "r"(ad));
            }
#pragma unroll
            for (int nt = 0; nt < 4; nt++) {
                int r = brow + nt * 8;
                unsigned bd = sb + (unsigned)(ASZ * 4) +
                              (unsigned)(r * 128 + (((2 * ks + bcs) ^ (r & 7)) << 4));
                asm volatile(
                    "ldmatrix.sync.aligned.m8n8.x2.shared.b16 {%0,%1}, [%2];"
                    : "=r"(bf[nt][0]), "=r"(bf[nt][1])
                    : "r"(bd));
            }
#pragma unroll
            for (int mt = 0; mt < 4; mt++)
#pragma unroll
                for (int nt = 0; nt < 4; nt++)
                    asm volatile(
                        "mma.sync.aligned.m16n8k16.row.col.f32.f16.f16.f32 "
                        "{%0,%1,%2,%3}, {%4,%5,%6,%7}, {%8,%9}, {%0,%1,%2,%3};"
                        : "+f"(acc[mt][nt][0]), "+f"(acc[mt][nt][1]),
                          "+f"(acc[mt][nt][2]), "+f"(acc[mt][nt][3])
                        : "r"(a[mt][0]), "r"(a[mt][1]), "r"(a[mt][2]), "r"(a[mt][3]),
                          "r"(bf[nt][0]), "r"(bf[nt][1]));
        }
    }

    const int gg = lane >> 2, tt = lane & 3;
#pragma unroll
    for (int mt = 0; mt < 4; mt++) {
        int r = row0 + wm * 64 + mt * 16 + gg;
#pragma unroll
        for (int nt = 0; nt < 4; nt++) {
            int cc = col0 + wn * 32 + nt * 8 + 2 * tt;
            *(float2*)&C[(size_t)r * N + cc]       = make_float2(acc[mt][nt][0], acc[mt][nt][1]);
            *(float2*)&C[(size_t)(r + 8) * N + cc] = make_float2(acc[mt][nt][2], acc[mt][nt][3]);
        }
    }
}

// ============================================================================
// Fused conv+SiLU+SSD. G = (C B^T).*causal now computed with fp16 MMA:
// conv emits SW128-swizzled fp16 C/B tiles; 8 warps compute 16x32 stripes of
// G (m16n8k16), causal mask applied in the epilogue from fragment coords
// (also kills the Gs zero-fill). Y phase and chunk state remain fp32.
// ============================================================================
#define SPAD 68
#define TSZ  (64 * SPAD)
// floats: Xs + Bs + Gs (3*TSZ) then fp16 area: CsH(64x64) + BsH(64x64)
#define H16_OFF (3 * TSZ)
#define SSD_SMEM ((3 * TSZ + 4096) * 4)    // 68608 B

__global__ __launch_bounds__(256, 2) void ssd_chunk_kernel(
    const float* __restrict__ zxbc, const float* __restrict__ cw,
    const float* __restrict__ cb,   float* __restrict__ xbca,
    float* __restrict__ ydiag,      float* __restrict__ cs)
{
    extern __shared__ float ssm[];
    float* Xs = ssm;
    float* Bs = ssm + TSZ;
    float* Gs = ssm + 2 * TSZ;
    char*  CsH = (char*)(ssm + H16_OFF);        // 8192 B, SW128 swizzled fp16
    char*  BsH = CsH + 8192;                    // 8192 B

    int bid = blockIdx.x;
    int c  = bid & 63;
    int bh = bid >> 6;
    int h  = bh & 31;
    int b  = bh >> 5;
    int sl0 = c * CHUNK;
    size_t rbase = (size_t)b * SEQ + sl0;
    int tid = threadIdx.x;

    // ---- conv + silu for x, B, C ----
#pragma unroll
    for (int reg = 0; reg < 3; reg++) {
        int chbase = reg * 2048 + h * 64;
        for (int i = tid; i < 64 * 16; i += 256) {
            int l = i >> 4, q = (i & 15) * 4;
            size_t r = rbase + l;
            int sl = sl0 + l;
            const float* p = zxbc + r * ZXB_LD + DMODEL + chbase + q;
            float4 x0 = *(const float4*)p;
            float4 xm = (sl > 0)       ? *(const float4*)(p - ZXB_LD) : make_float4(0.f,0.f,0.f,0.f);
            float4 xp = (sl < SEQ - 1) ? *(const float4*)(p + ZXB_LD) : make_float4(0.f,0.f,0.f,0.f);
            int ch = chbase + q;
            float4 v;
            v.x = fmaf(cw[3*ch+0], xm.x, fmaf(cw[3*ch+1], x0.x, fmaf(cw[3*ch+2], xp.x, cb[ch])));
            v.y = fmaf(cw[3*ch+3], xm.y, fmaf(cw[3*ch+4], x0.y, fmaf(cw[3*ch+5], xp.y, cb[ch+1])));
            v.z = fmaf(cw[3*ch+6], xm.z, fmaf(cw[3*ch+7], x0.z, fmaf(cw[3*ch+8], xp.z, cb[ch+2])));
            v.w = fmaf(cw[3*ch+9], xm.w, fmaf(cw[3*ch+10], x0.w, fmaf(cw[3*ch+11], xp.w, cb[ch+3])));
            v.x = silu(v.x); v.y = silu(v.y); v.z = silu(v.z); v.w = silu(v.w);

            if (reg == 0) {
                *(float4*)&Xs[l * SPAD + q] = v;
            } else {
                // fp16 pack (4 halves = 8B) into SW128-swizzled tile
                __half2 lo = __floats2half2_rn(v.x, v.y);
                __half2 hi = __floats2half2_rn(v.z, v.w);
                uint2 hv;
                hv.x = *(unsigned*)&lo;
                hv.y = *(unsigned*)&hi;
                int cc = q >> 3;
                int off = (q & 4) << 1;       // 0 or 8 bytes within the 16B chunk
                int addr = l * 128 + ((cc ^ (l & 7)) << 4) + off;
                if (reg == 1) {
                    *(float4*)&Bs[l * SPAD + q] = v;     // fp32 B kept for chunk state
                    *(uint2*)(BsH + addr) = hv;
                } else {
                    *(uint2*)(CsH + addr) = hv;
                    *(float4*)&xbca[r * CONVD + 2 * DMODEL + h * 64 + q] = v;
                }
            }
        }
    }
    __syncthreads();

    // ---- G = C . B^T via fp16 MMA; causal mask in epilogue ----
    {
        const int wid  = tid >> 5, lane = tid & 31;
        const int wrow = (wid & 3) * 16;       // 16-row stripe
        const int wcol = (wid >> 2) * 32;      // 32-col half
        const unsigned cBase = (unsigned)__cvta_generic_to_shared(CsH);
        const unsigned bBase = (unsigned)__cvta_generic_to_shared(BsH);
        const int ar = wrow + (lane & 15);
        const int acsl = lane >> 4;
        const int br0 = wcol + (lane & 7);
        const int bcsl = (lane >> 3) & 1;

        float acc[4][4];
#pragma unroll
        for (int i = 0; i < 4; i++)
#pragma unroll
            for (int j = 0; j < 4; j++) acc[i][j] = 0.f;

#pragma unroll
        for (int ks = 0; ks < 4; ks++) {
            unsigned a[4];
            unsigned ad = cBase + (unsigned)(ar * 128 + (((2 * ks + acsl) ^ (ar & 7)) << 4));
            asm volatile(
                "ldmatrix.sync.aligned.m8n8.x4.shared.b16 {%0,%1,%2,%3}, [%4];"
                : "=r"(a[0]), "=r"(a[1]), "=r"(a[2]), "=r"(a[3]) : "r"(ad));
#pragma unroll
            for (int nt = 0; nt < 4; nt++) {
                int rr = br0 + nt * 8;
                unsigned bd = bBase + (unsigned)(rr * 128 + (((2 * ks + bcsl) ^ (rr & 7)) << 4));
                unsigned bf0, bf1;
                asm volatile(
                    "ldmatrix.sync.aligned.m8n8.x2.shared.b16 {%0,%1}, [%2];"
                    : "=r"(bf0), "=r"(bf1) : "r"(bd));
                asm volatile(
                    "mma.sync.aligned.m16n8k16.row.col.f32.f16.f16.f32 "
                    "{%0,%1,%2,%3}, {%4,%5,%6,%7}, {%8,%9}, {%0,%1,%2,%3};"
                    : "+f"(acc[nt][0]), "+f"(acc[nt][1]), "+f"(acc[nt][2]), "+f"(acc[nt][3])
                    : "r"(a[0]), "r"(a[1]), "r"(a[2]), "r"(a[3]), "r"(bf0), "r"(bf1));
            }
        }
        const int g = lane >> 2, t4 = lane & 3;
        int r0 = wrow + g, r1 = r0 + 8;
#pragma unroll
        for (int nt = 0; nt < 4; nt++) {
            int c0 = wcol + nt * 8 + 2 * t4, c1 = c0 + 1;
            Gs[r0 * SPAD + c0] = (r0 >= c0) ? acc[nt][0] : 0.f;
            Gs[r0 * SPAD + c1] = (r0 >= c1) ? acc[nt][1] : 0.f;
            Gs[r1 * SPAD + c0] = (r1 >= c0) ? acc[nt][2] : 0.f;
            Gs[r1 * SPAD + c1] = (r1 >= c1) ? acc[nt][3] : 0.f;
        }
    }
    __syncthreads();

    // ---- Y[l][p] = sum_m G[l][m] x[m][p] ; 2 rows x 8 cols per thread ----
    {
        const int lt = tid & 31;
        const int qt = tid >> 5;
        float4 a00 = make_float4(0.f,0.f,0.f,0.f), a01 = a00;
        float4 a10 = a00, a11 = a00;
        const float* gr0 = &Gs[lt * SPAD];
        const float* gr1 = &Gs[(lt + 32) * SPAD];
#pragma unroll 4
        for (int m = 0; m < 64; m++) {
            const float* xr = &Xs[m * SPAD + qt * 8];
            float4 x0 = *(const float4*)&xr[0];
            float4 x1 = *(const float4*)&xr[4];
            float g0 = gr0[m], g1 = gr1[m];
            a00.x = fmaf(g0, x0.x, a00.x); a00.y = fmaf(g0, x0.y, a00.y);
            a00.z = fmaf(g0, x0.z, a00.z); a00.w = fmaf(g0, x0.w, a00.w);
            a01.x = fmaf(g0, x1.x, a01.x); a01.y = fmaf(g0, x1.y, a01.y);
            a01.z = fmaf(g0, x1.z, a01.z); a01.w = fmaf(g0, x1.w, a01.w);
            a10.x = fmaf(g1, x0.x, a10.x); a10.y = fmaf(g1, x0.y, a10.y);
            a10.z = fmaf(g1, x0.z, a10.z); a10.w = fmaf(g1, x0.w, a10.w);
            a11.x = fmaf(g1, x1.x, a11.x); a11.y = fmaf(g1, x1.y, a11.y);
            a11.z = fmaf(g1, x1.z, a11.z); a11.w = fmaf(g1, x1.w, a11.w);
        }
        float* yr0 = &ydiag[(rbase + lt) * DMODEL + h * 64 + qt * 8];
        float* yr1 = &ydiag[(rbase + lt + 32) * DMODEL + h * 64 + qt * 8];
        *(float4*)&yr0[0] = a00;
        *(float4*)&yr0[4] = a01;
        *(float4*)&yr1[0] = a10;
        *(float4*)&yr1[4] = a11;
    }

    // ---- chunk state (fp32) ----
    if (tid < 64) {
        float a = 0.f;
#pragma unroll 8
        for (int ll = 0; ll < 64; ll++)
            a = fmaf(Xs[ll * SPAD + tid], Bs[ll * SPAD + tid], a);
        cs[(size_t)bid * 64 + tid] = a;
    }
}

// ============================================================================
// Inter-chunk scan (constant decay exp(63*A_log[h]) per head)
// ============================================================================
__global__ void scan_kernel(const float* __restrict__ cs, const float* __restrict__ A_log,
                            float* __restrict__ prev)
{
    int bh = blockIdx.x;
    int h  = bh & 31;
    int n  = threadIdx.x;
    float d = expf(63.f * A_log[h]);
    float s = 0.f;
    for (int c = 0; c < NCHUNK; c++) {
        size_t idx = ((size_t)bh * NCHUNK + c) * 64 + n;
        prev[idx] = s;
        s = s * d + cs[idx];
    }
}

// ============================================================================
// Y = Y_diag + Y_off; gate with silu(z); RMSNorm. Output fp16.
// ============================================================================
__global__ __launch_bounds__(256) void combine_kernel(
    const float* __restrict__ ydiag, const float* __restrict__ zxbc,
    const float* __restrict__ xbca,  const float* __restrict__ prev,
    const float* __restrict__ rms_w, __half* __restrict__ yn)
{
    int r = blockIdx.x;
    int b = r >> 12;
    int l = r & (SEQ - 1);
    int c = l >> 6;

    __shared__ float sh_yoff[NHEADS];
    __shared__ float sh_red[8];

    int tid = threadIdx.x, warp = tid >> 5, lane = tid & 31;

    for (int h = warp; h < NHEADS; h += 8) {
        const float* Crow = xbca + (size_t)r * CONVD + 2 * DMODEL + h * 64;
        const float* pv   = prev + ((size_t)(b * NHEADS + h) * NCHUNK + c) * 64;
        int n0 = lane * 2;
        float v = Crow[n0] * pv[n0] + Crow[n0 + 1] * pv[n0 + 1];
#pragma unroll
        for (int o = 16; o; o >>= 1) v += __shfl_down_sync(0xffffffffu, v, o);
        if (lane == 0) sh_yoff[h] = v;
    }
    __syncthreads();

    float vals[8];
    float ss = 0.f;
#pragma unroll
    for (int j = 0; j < 8; j++) {
        int d = tid + j * 256;
        float z  = zxbc[(size_t)r * ZXB_LD + d];
        float sz = z / (1.f + expf(-z));
        float y  = (ydiag[(size_t)r * DMODEL + d] + sh_yoff[d >> 6]) * sz;
        vals[j] = y;
        ss += y * y;
    }
#pragma unroll
    for (int o = 16; o; o >>= 1) ss += __shfl_down_sync(0xffffffffu, ss, o);
    if (lane == 0) sh_red[warp] = ss;
    __syncthreads();
    if (tid == 0) {
        float t = 0.f;
#pragma unroll
        for (int w = 0; w < 8; w++) t += sh_red[w];
        sh_red[0] = rsqrtf(t / (float)DMODEL + RMS_EPS);
    }
    __syncthreads();
    float scale = sh_red[0];
#pragma unroll
    for (int j = 0; j < 8; j++) {
        int d = tid + j * 256;
        yn[(size_t)r * DMODEL + d] = __float2half_rn(vals[j] * scale * rms_w[d]);
    }
}

// ============================================================================
// launch
// ============================================================================
extern "C" void kernel_launch(void* const* d_in, const int* in_sizes, int n_in,
                              void* d_out, int out_size)
{
    const float* u      = (const float*)d_in[0];
    const float* W_in   = (const float*)d_in[1];
    const float* W_out  = (const float*)d_in[2];
    const float* conv_w = (const float*)d_in[3];
    const float* conv_b = (const float*)d_in[4];
    const float* A_log  = (const float*)d_in[5];
    const float* rms_w  = (const float*)d_in[6];
    float* out = (float*)d_out;

    float *zxbc, *xbca, *y, *cs, *prev;
    __half *yn, *ut, *wit, *wot;
    cudaGetSymbolAddress((void**)&zxbc, g_zxbc);
    cudaGetSymbolAddress((void**)&xbca, g_xbca);
    cudaGetSymbolAddress((void**)&y,    g_y);
    cudaGetSymbolAddress((void**)&yn,   g_yn);
    cudaGetSymbolAddress((void**)&cs,   g_cs);
    cudaGetSymbolAddress((void**)&prev, g_prev);
    cudaGetSymbolAddress((void**)&ut,   g_ut);
    cudaGetSymbolAddress((void**)&wit,  g_wit);
    cudaGetSymbolAddress((void**)&wot,  g_wot);

    static bool attr_done = false;
    if (!attr_done) {
        cudaFuncSetAttribute(gemm_tn_f16, cudaFuncAttributeMaxDynamicSharedMemorySize, GSMEM);
        cudaFuncSetAttribute(ssd_chunk_kernel, cudaFuncAttributeMaxDynamicSharedMemorySize, SSD_SMEM);
        attr_done = true;
    }

    // 0) convert operands to fp16
    {
        size_t n4u = (size_t)ROWS * DMODEL / 4;
        h_convert<<<(unsigned)((n4u + 255) / 256), 256>>>(u, ut, n4u);
        size_t n4w = (size_t)ZXB_LD * DMODEL / 4;
        h_convert<<<(unsigned)((n4w + 255) / 256), 256>>>(W_in, wit, n4w);
        size_t n4o = (size_t)DMODEL * DMODEL / 4;
        h_convert<<<(unsigned)((n4o + 255) / 256), 256>>>(W_out, wot, n4o);
    }
    // 1) zxbc = u @ W_in^T (first 8192 output cols; dt cols unused)
    gemm_tn_f16<<<dim3(ZXB_LD / 128, ROWS / 128), 256, GSMEM>>>(ut, wit, zxbc, ROWS, ZXB_LD, DMODEL);
    // 2) fused conv + silu + per-chunk SSD (G via fp16 MMA)
    ssd_chunk_kernel<<<BATCH * NHEADS * NCHUNK, 256, SSD_SMEM>>>(zxbc, conv_w, conv_b, xbca, y, cs);
    // 3) inter-chunk scan
    scan_kernel<<<BATCH * NHEADS, 64>>>(cs, A_log, prev);
    // 4) Y_off + gate + rmsnorm (writes fp16)
    combine_kernel<<<ROWS, 256>>>(y, zxbc, xbca, prev, rms_w, yn);
    // 5) out = yn @ W_out^T
    gemm_tn_f16<<<dim3(DMODEL / 128, ROWS / 128), 256, GSMEM>>>(yn, wot, out, ROWS, DMODEL, DMODEL);
}

// round 13
// speedup vs baseline: 1.1922x; 1.0063x over previous
#include <cuda_runtime.h>
#include <cuda_fp16.h>
#include <math.h>
#include <stdint.h>

// ---------------- constants ----------------
#define BATCH   2
#define SEQ     4096
#define ROWS    (BATCH*SEQ)        // 8192
#define DMODEL  2048
#define DSTATE  64
#define DHEAD   64
#define NHEADS  32
#define CHUNK   64
#define NCHUNK  (SEQ/CHUNK)        // 64
#define CONVD   6144
#define ZXB_LD  8192               // output cols of GEMM1 (dt cols unused)
#define RMS_EPS 1.1920929e-07f

// ---------------- scratch ----------------
__device__ float  g_z   [(size_t)ROWS * DMODEL];   // z (gate input), fp32
__device__ __half g_xbch[(size_t)ROWS * CONVD];    // xBC pre-conv, fp16
__device__ __half g_ch  [(size_t)ROWS * DMODEL];   // silu(conv(C)) compact, fp16
__device__ __half g_y   [(size_t)ROWS * DMODEL];   // Y_diag, fp16
__device__ __half g_yn  [(size_t)ROWS * DMODEL];   // gated+rmsnormed, fp16
__device__ float  g_cs  [(size_t)BATCH*NHEADS*NCHUNK*DSTATE];
__device__ float  g_prev[(size_t)BATCH*NHEADS*NCHUNK*DSTATE];
__device__ __half g_ut  [(size_t)ROWS * DMODEL];
__device__ __half g_wit [(size_t)ZXB_LD * DMODEL];
__device__ __half g_wot [(size_t)DMODEL * DMODEL];

// ---------------- helpers ----------------
__device__ __forceinline__ void cp16(void* dst, const void* src) {
    unsigned saddr = (unsigned)__cvta_generic_to_shared(dst);
    asm volatile("cp.async.cg.shared.global [%0], [%1], 16;" :: "r"(saddr), "l"(src));
}
__device__ __forceinline__ float silu(float v) { return v / (1.f + expf(-v)); }

__global__ void h_convert(const float* __restrict__ in, __half* __restrict__ out, size_t n4)
{
    size_t i = (size_t)blockIdx.x * blockDim.x + threadIdx.x;
    if (i >= n4) return;
    float4 v = ((const float4*)in)[i];
    __half2 lo = __floats2half2_rn(v.x, v.y);
    __half2 hi = __floats2half2_rn(v.z, v.w);
    uint2 o;
    o.x = *(unsigned*)&lo;
    o.y = *(unsigned*)&hi;
    ((uint2*)out)[i] = o;
}

// ============================================================================
// GEMM (proven config): C[M,N] = A[M,K] * B[N,K]^T ; fp16 in, fp32 acc.
// Block 128x128, warp tile 64x32 (8 warps 2x4), K-tile 64, SW128 swizzle,
// m16n8k16, 3-stage cp.async ring, one sync per K-tile, 2 CTAs/SM.
// SPLIT=true: cols <2048 -> fp32 Cz[ROWS,2048]; cols >=2048 -> fp16
// Ch[ROWS,CONVD] at col-2048 (GEMM1). SPLIT=false: plain fp32 Cz (GEMM2/out).
// ============================================================================
#define NSTG  3
#define KT    64
#define ASZ   (128 * 32)
#define STG   (2 * ASZ)
#define GSMEM (NSTG * STG * 4)      // 98304 B

template<bool SPLIT>
__global__ __launch_bounds__(256, 2) void gemm_tn_f16(
    const __half* __restrict__ A, const __half* __restrict__ B,
    float* __restrict__ Cz, __half* __restrict__ Ch, int M, int N, int K)
{
    extern __shared__ __align__(16) unsigned sm[];

    const int tid  = threadIdx.x;
    const int row0 = blockIdx.y * 128;
    const int col0 = blockIdx.x * 128;
    const int warp = tid >> 5, lane = tid & 31;
    const int wm = warp >> 2, wn = warp & 3;

    float acc[4][4][4];
#pragma unroll
    for (int i = 0; i < 4; i++)
#pragma unroll
        for (int j = 0; j < 4; j++)
#pragma unroll
            for (int k = 0; k < 4; k++) acc[i][j][k] = 0.f;

    const __half* Ag = A + (size_t)row0 * K;
    const __half* Bg = B + (size_t)col0 * K;
    const int NT = K / KT;

    auto issue = [&](int j) {
        unsigned* as = sm + (j % NSTG) * STG;
        unsigned* bs = as + ASZ;
        int k0 = j * KT;
#pragma unroll
        for (int i = 0; i < 4; i++) {
            int ch = tid + i * 256;
            int r = ch >> 3, c = ch & 7;
            cp16(&as[r * 32 + ((c ^ (r & 7)) << 2)], Ag + (size_t)r * K + k0 + c * 8);
        }
#pragma unroll
        for (int i = 0; i < 4; i++) {
            int ch = tid + i * 256;
            int r = ch >> 3, c = ch & 7;
            cp16(&bs[r * 32 + ((c ^ (r & 7)) << 2)], Bg + (size_t)r * K + k0 + c * 8);
        }
        asm volatile("cp.async.commit_group;");
    };

    issue(0);
    if (NT > 1) issue(1);

    const unsigned smb = (unsigned)__cvta_generic_to_shared(sm);
    const int arow = wm * 64 + (lane & 15);
    const int acs  = lane >> 4;
    const int brow = wn * 32 + (lane & 7);
    const int bcs  = (lane >> 3) & 1;

    for (int t = 0; t < NT; t++) {
        if (t + 1 < NT) {
            asm volatile("cp.async.wait_group 1;");
        } else {
            asm volatile("cp.async.wait_group 0;");
        }
        __syncthreads();
        if (t + 2 < NT) issue(t + 2);

        const unsigned sb = smb + (unsigned)(t % NSTG) * (STG * 4);

#pragma unroll
        for (int ks = 0; ks < 4; ks++) {
            unsigned a[4][4], bf[4][2];
#pragma unroll
            for (int mt = 0; mt < 4; mt++) {
                int r = arow + mt * 16;
                unsigned ad = sb + (unsigned)(r * 128 + (((2 * ks + acs) ^ (r & 7)) << 4));
                asm volatile(
                    "ldmatrix.sync.aligned.m8n8.x4.shared.b16 {%0,%1,%2,%3}, [%4];"
                    : "=r"(a[mt][0]), "=r"(a[mt][1]), "=r"(a[mt][2]), "=r"(a[mt][3])
                    : "r"(ad));
            }
#pragma unroll
            for (int nt = 0; nt < 4; nt++) {
                int r = brow + nt * 8;
                unsigned bd = sb + (unsigned)(ASZ * 4) +
                              (unsigned)(r * 128 + (((2 * ks + bcs) ^ (r & 7)) << 4));
                asm volatile(
                    "ldmatrix.sync.aligned.m8n8.x2.shared.b16 {%0,%1}, [%2];"
                    : "=r"(bf[nt][0]), "=r"(bf[nt][1])
                    : "r"(bd));
            }
#pragma unroll
            for (int mt = 0; mt < 4; mt++)
#pragma unroll
                for (int nt = 0; nt < 4; nt++)
                    asm volatile(
                        "mma.sync.aligned.m16n8k16.row.col.f32.f16.f16.f32 "
                        "{%0,%1,%2,%3}, {%4,%5,%6,%7}, {%8,%9}, {%0,%1,%2,%3};"
                        : "+f"(acc[mt][nt][0]), "+f"(acc[mt][nt][1]),
                          "+f"(acc[mt][nt][2]), "+f"(acc[mt][nt][3])
                        : "r"(a[mt][0]), "r"(a[mt][1]), "r"(a[mt][2]), "r"(a[mt][3]),
                          "r"(bf[nt][0]), "r"(bf[nt][1]));
        }
    }

    const int gg = lane >> 2, tt = lane & 3;
    if (!SPLIT) {
#pragma unroll
        for (int mt = 0; mt < 4; mt++) {
            int r = row0 + wm * 64 + mt * 16 + gg;
#pragma unroll
            for (int nt = 0; nt < 4; nt++) {
                int cc = col0 + wn * 32 + nt * 8 + 2 * tt;
                *(float2*)&Cz[(size_t)r * N + cc]       = make_float2(acc[mt][nt][0], acc[mt][nt][1]);
                *(float2*)&Cz[(size_t)(r + 8) * N + cc] = make_float2(acc[mt][nt][2], acc[mt][nt][3]);
            }
        }
    } else if (col0 < DMODEL) {
        // z region: fp32 compact [ROWS, DMODEL]
#pragma unroll
        for (int mt = 0; mt < 4; mt++) {
            int r = row0 + wm * 64 + mt * 16 + gg;
#pragma unroll
            for (int nt = 0; nt < 4; nt++) {
                int cc = col0 + wn * 32 + nt * 8 + 2 * tt;
                *(float2*)&Cz[(size_t)r * DMODEL + cc]       = make_float2(acc[mt][nt][0], acc[mt][nt][1]);
                *(float2*)&Cz[(size_t)(r + 8) * DMODEL + cc] = make_float2(acc[mt][nt][2], acc[mt][nt][3]);
            }
        }
    } else {
        // xBC region: fp16 [ROWS, CONVD]
#pragma unroll
        for (int mt = 0; mt < 4; mt++) {
            int r = row0 + wm * 64 + mt * 16 + gg;
#pragma unroll
            for (int nt = 0; nt < 4; nt++) {
                int cc = col0 - DMODEL + wn * 32 + nt * 8 + 2 * tt;
                __half2 h0 = __floats2half2_rn(acc[mt][nt][0], acc[mt][nt][1]);
                __half2 h1 = __floats2half2_rn(acc[mt][nt][2], acc[mt][nt][3]);
                *(__half2*)&Ch[(size_t)r * CONVD + cc]       = h0;
                *(__half2*)&Ch[(size_t)(r + 8) * CONVD + cc] = h1;
            }
        }
    }
}

// ============================================================================
// Fused conv+SiLU+SSD. Reads fp16 xBC; conv in fp32; G via fp16 MMA with
// causal mask in epilogue; Y phase fp32 FMA; outputs ydiag fp16 + compact
// fp16 C tile; chunk state fp32.
// ============================================================================
#define SPAD 68
#define TSZ  (64 * SPAD)
#define H16_OFF (3 * TSZ)
#define SSD_SMEM ((3 * TSZ + 4096) * 4)    // 68608 B

__global__ __launch_bounds__(256, 2) void ssd_chunk_kernel(
    const __half* __restrict__ xbch, const float* __restrict__ cw,
    const float* __restrict__ cb,    __half* __restrict__ chx,
    __half* __restrict__ ydiag,      float* __restrict__ cs)
{
    extern __shared__ float ssm[];
    float* Xs = ssm;
    float* Bs = ssm + TSZ;
    float* Gs = ssm + 2 * TSZ;
    char*  CsH = (char*)(ssm + H16_OFF);   // SW128 swizzled fp16 C
    char*  BsH = CsH + 8192;               // SW128 swizzled fp16 B

    int bid = blockIdx.x;
    int c  = bid & 63;
    int bh = bid >> 6;
    int h  = bh & 31;
    int b  = bh >> 5;
    int sl0 = c * CHUNK;
    size_t rbase = (size_t)b * SEQ + sl0;
    int tid = threadIdx.x;

    // ---- conv + silu for x, B, C (fp16 input) ----
#pragma unroll
    for (int reg = 0; reg < 3; reg++) {
        int chbase = reg * 2048 + h * 64;
        for (int i = tid; i < 64 * 16; i += 256) {
            int l = i >> 4, q = (i & 15) * 4;
            size_t r = rbase + l;
            int sl = sl0 + l;
            const __half* p = xbch + r * CONVD + chbase + q;
            uint2 u0 = *(const uint2*)p;
            uint2 um = (sl > 0)       ? *(const uint2*)(p - CONVD) : make_uint2(0u, 0u);
            uint2 up = (sl < SEQ - 1) ? *(const uint2*)(p + CONVD) : make_uint2(0u, 0u);
            __half2 h0a = *(__half2*)&u0.x, h0b = *(__half2*)&u0.y;
            __half2 hma = *(__half2*)&um.x, hmb = *(__half2*)&um.y;
            __half2 hpa = *(__half2*)&up.x, hpb = *(__half2*)&up.y;
            float4 x0 = make_float4(__low2float(h0a), __high2float(h0a),
                                    __low2float(h0b), __high2float(h0b));
            float4 xm = make_float4(__low2float(hma), __high2float(hma),
                                    __low2float(hmb), __high2float(hmb));
            float4 xp = make_float4(__low2float(hpa), __high2float(hpa),
                                    __low2float(hpb), __high2float(hpb));
            int ch = chbase + q;
            float4 v;
            v.x = fmaf(cw[3*ch+0], xm.x, fmaf(cw[3*ch+1], x0.x, fmaf(cw[3*ch+2], xp.x, cb[ch])));
            v.y = fmaf(cw[3*ch+3], xm.y, fmaf(cw[3*ch+4], x0.y, fmaf(cw[3*ch+5], xp.y, cb[ch+1])));
            v.z = fmaf(cw[3*ch+6], xm.z, fmaf(cw[3*ch+7], x0.z, fmaf(cw[3*ch+8], xp.z, cb[ch+2])));
            v.w = fmaf(cw[3*ch+9], xm.w, fmaf(cw[3*ch+10], x0.w, fmaf(cw[3*ch+11], xp.w, cb[ch+3])));
            v.x = silu(v.x); v.y = silu(v.y); v.z = silu(v.z); v.w = silu(v.w);

            if (reg == 0) {
                *(float4*)&Xs[l * SPAD + q] = v;
            } else {
                __half2 lo = __floats2half2_rn(v.x, v.y);
                __half2 hi = __floats2half2_rn(v.z, v.w);
                uint2 hv;
                hv.x = *(unsigned*)&lo;
                hv.y = *(unsigned*)&hi;
                int cc2 = q >> 3;
                int off = (q & 4) << 1;
                int addr = l * 128 + ((cc2 ^ (l & 7)) << 4) + off;
                if (reg == 1) {
                    *(float4*)&Bs[l * SPAD + q] = v;
                    *(uint2*)(BsH + addr) = hv;
                } else {
                    *(uint2*)(CsH + addr) = hv;
                    *(uint2*)&chx[r * DMODEL + h * 64 + q] = hv;
                }
            }
        }
    }
    __syncthreads();

    // ---- G = C . B^T via fp16 MMA; causal mask in epilogue ----
    {
        const int wid  = tid >> 5, lane = tid & 31;
        const int wrow = (wid & 3) * 16;
        const int wcol = (wid >> 2) * 32;
        const unsigned cBase = (unsigned)__cvta_generic_to_shared(CsH);
        const unsigned bBase = (unsigned)__cvta_generic_to_shared(BsH);
        const int ar = wrow + (lane & 15);
        const int acsl = lane >> 4;
        const int br0 = wcol + (lane & 7);
        const int bcsl = (lane >> 3) & 1;

        float acc[4][4];
#pragma unroll
        for (int i = 0; i < 4; i++)
#pragma unroll
            for (int j = 0; j < 4; j++) acc[i][j] = 0.f;

#pragma unroll
        for (int ks = 0; ks < 4; ks++) {
            unsigned a[4];
            unsigned ad = cBase + (unsigned)(ar * 128 + (((2 * ks + acsl) ^ (ar & 7)) << 4));
            asm volatile(
                "ldmatrix.sync.aligned.m8n8.x4.shared.b16 {%0,%1,%2,%3}, [%4];"
                : "=r"(a[0]), "=r"(a[1]), "=r"(a[2]), "=r"(a[3]) : "r"(ad));
#pragma unroll
            for (int nt = 0; nt < 4; nt++) {
                int rr = br0 + nt * 8;
                unsigned bd = bBase + (unsigned)(rr * 128 + (((2 * ks + bcsl) ^ (rr & 7)) << 4));
                unsigned bf0, bf1;
                asm volatile(
                    "ldmatrix.sync.aligned.m8n8.x2.shared.b16 {%0,%1}, [%2];"
                    : "=r"(bf0), "=r"(bf1) : "r"(bd));
                asm volatile(
                    "mma.sync.aligned.m16n8k16.row.col.f32.f16.f16.f32 "
                    "{%0,%1,%2,%3}, {%4,%5,%6,%7}, {%8,%9}, {%0,%1,%2,%3};"
                    : "+f"(acc[nt][0]), "+f"(acc[nt][1]), "+f"(acc[nt][2]), "+f"(acc[nt][3])
                    : "r"(a[0]), "r"(a[1]), "r"(a[2]), "r"(a[3]), "r"(bf0), "r"(bf1));
            }
        }
        const int g = lane >> 2, t4 = lane & 3;
        int r0 = wrow + g, r1 = r0 + 8;
#pragma unroll
        for (int nt = 0; nt < 4; nt++) {
            int c0 = wcol + nt * 8 + 2 * t4, c1 = c0 + 1;
            Gs[r0 * SPAD + c0] = (r0 >= c0) ? acc[nt][0] : 0.f;
            Gs[r0 * SPAD + c1] = (r0 >= c1) ? acc[nt][1] : 0.f;
            Gs[r1 * SPAD + c0] = (r1 >= c0) ? acc[nt][2] : 0.f;
            Gs[r1 * SPAD + c1] = (r1 >= c1) ? acc[nt][3] : 0.f;
        }
    }
    __syncthreads();

    // ---- Y[l][p] = sum_m G[l][m] x[m][p] ; 2 rows x 8 cols per thread ----
    {
        const int lt = tid & 31;
        const int qt = tid >> 5;
        float4 a00 = make_float4(0.f,0.f,0.f,0.f), a01 = a00;
        float4 a10 = a00, a11 = a00;
        const float* gr0 = &Gs[lt * SPAD];
        const float* gr1 = &Gs[(lt + 32) * SPAD];
#pragma unroll 4
        for (int m = 0; m < 64; m++) {
            const float* xr = &Xs[m * SPAD + qt * 8];
            float4 x0 = *(const float4*)&xr[0];
            float4 x1 = *(const float4*)&xr[4];
            float g0 = gr0[m], g1 = gr1[m];
            a00.x = fmaf(g0, x0.x, a00.x); a00.y = fmaf(g0, x0.y, a00.y);
            a00.z = fmaf(g0, x0.z, a00.z); a00.w = fmaf(g0, x0.w, a00.w);
            a01.x = fmaf(g0, x1.x, a01.x); a01.y = fmaf(g0, x1.y, a01.y);
            a01.z = fmaf(g0, x1.z, a01.z); a01.w = fmaf(g0, x1.w, a01.w);
            a10.x = fmaf(g1, x0.x, a10.x); a10.y = fmaf(g1, x0.y, a10.y);
            a10.z = fmaf(g1, x0.z, a10.z); a10.w = fmaf(g1, x0.w, a10.w);
            a11.x = fmaf(g1, x1.x, a11.x); a11.y = fmaf(g1, x1.y, a11.y);
            a11.z = fmaf(g1, x1.z, a11.z); a11.w = fmaf(g1, x1.w, a11.w);
        }
        __half2 p0 = __floats2half2_rn(a00.x, a00.y);
        __half2 p1 = __floats2half2_rn(a00.z, a00.w);
        __half2 p2 = __floats2half2_rn(a01.x, a01.y);
        __half2 p3 = __floats2half2_rn(a01.z, a01.w);
        uint2 w0 = make_uint2(*(unsigned*)&p0, *(unsigned*)&p1);
        uint2 w1 = make_uint2(*(unsigned*)&p2, *(unsigned*)&p3);
        __half2 q0 = __floats2half2_rn(a10.x, a10.y);
        __half2 q1 = __floats2half2_rn(a10.z, a10.w);
        __half2 q2 = __floats2half2_rn(a11.x, a11.y);
        __half2 q3 = __floats2half2_rn(a11.z, a11.w);
        uint2 w2 = make_uint2(*(unsigned*)&q0, *(unsigned*)&q1);
        uint2 w3 = make_uint2(*(unsigned*)&q2, *(unsigned*)&q3);
        __half* yr0 = &ydiag[(rbase + lt) * DMODEL + h * 64 + qt * 8];
        __half* yr1 = &ydiag[(rbase + lt + 32) * DMODEL + h * 64 + qt * 8];
        *(uint2*)&yr0[0] = w0;
        *(uint2*)&yr0[4] = w1;
        *(uint2*)&yr1[0] = w2;
        *(uint2*)&yr1[4] = w3;
    }

    // ---- chunk state (fp32) ----
    if (tid < 64) {
        float a = 0.f;
#pragma unroll 8
        for (int ll = 0; ll < 64; ll++)
            a = fmaf(Xs[ll * SPAD + tid], Bs[ll * SPAD + tid], a);
        cs[(size_t)bid * 64 + tid] = a;
    }
}

// ============================================================================
// Inter-chunk scan (constant decay exp(63*A_log[h]) per head)
// ============================================================================
__global__ void scan_kernel(const float* __restrict__ cs, const float* __restrict__ A_log,
                            float* __restrict__ prev)
{
    int bh = blockIdx.x;
    int h  = bh & 31;
    int n  = threadIdx.x;
    float d = expf(63.f * A_log[h]);
    float s = 0.f;
    for (int c = 0; c < NCHUNK; c++) {
        size_t idx = ((size_t)bh * NCHUNK + c) * 64 + n;
        prev[idx] = s;
        s = s * d + cs[idx];
    }
}

// ============================================================================
// Y = Y_diag + Y_off; gate with silu(z); RMSNorm. fp16 inputs, fp32 math.
// ============================================================================
__global__ __launch_bounds__(256) void combine_kernel(
    const __half* __restrict__ ydiag, const float* __restrict__ gz,
    const __half* __restrict__ chx,   const float* __restrict__ prev,
    const float* __restrict__ rms_w,  __half* __restrict__ yn)
{
    int r = blockIdx.x;
    int b = r >> 12;
    int l = r & (SEQ - 1);
    int c = l >> 6;

    __shared__ float sh_yoff[NHEADS];
    __shared__ float sh_red[8];

    int tid = threadIdx.x, warp = tid >> 5, lane = tid & 31;

    for (int h = warp; h < NHEADS; h += 8) {
        const __half* Crow = chx + (size_t)r * DMODEL + h * 64;
        const float* pv    = prev + ((size_t)(b * NHEADS + h) * NCHUNK + c) * 64;
        int n0 = lane * 2;
        float v = __half2float(Crow[n0]) * pv[n0] + __half2float(Crow[n0 + 1]) * pv[n0 + 1];
#pragma unroll
        for (int o = 16; o; o >>= 1) v += __shfl_down_sync(0xffffffffu, v, o);
        if (lane == 0) sh_yoff[h] = v;
    }
    __syncthreads();

    float vals[8];
    float ss = 0.f;
#pragma unroll
    for (int j = 0; j < 8; j++) {
        int d = tid + j * 256;
        float z  = gz[(size_t)r * DMODEL + d];
        float sz = z / (1.f + expf(-z));
        float y  = (__half2float(ydiag[(size_t)r * DMODEL + d]) + sh_yoff[d >> 6]) * sz;
        vals[j] = y;
        ss += y * y;
    }
#pragma unroll
    for (int o = 16; o; o >>= 1) ss += __shfl_down_sync(0xffffffffu, ss, o);
    if (lane == 0) sh_red[warp] = ss;
    __syncthreads();
    if (tid == 0) {
        float t = 0.f;
#pragma unroll
        for (int w = 0; w < 8; w++) t += sh_red[w];
        sh_red[0] = rsqrtf(t / (float)DMODEL + RMS_EPS);
    }
    __syncthreads();
    float scale = sh_red[0];
#pragma unroll
    for (int j = 0; j < 8; j++) {
        int d = tid + j * 256;
        yn[(size_t)r * DMODEL + d] = __float2half_rn(vals[j] * scale * rms_w[d]);
    }
}

// ============================================================================
// launch
// ============================================================================
extern "C" void kernel_launch(void* const* d_in, const int* in_sizes, int n_in,
                              void* d_out, int out_size)
{
    const float* u      = (const float*)d_in[0];
    const float* W_in   = (const float*)d_in[1];
    const float* W_out  = (const float*)d_in[2];
    const float* conv_w = (const float*)d_in[3];
    const float* conv_b = (const float*)d_in[4];
    const float* A_log  = (const float*)d_in[5];
    const float* rms_w  = (const float*)d_in[6];
    float* out = (float*)d_out;

    float *gz, *cs, *prev;
    __half *xbch, *chx, *y, *yn, *ut, *wit, *wot;
    cudaGetSymbolAddress((void**)&gz,   g_z);
    cudaGetSymbolAddress((void**)&xbch, g_xbch);
    cudaGetSymbolAddress((void**)&chx,  g_ch);
    cudaGetSymbolAddress((void**)&y,    g_y);
    cudaGetSymbolAddress((void**)&yn,   g_yn);
    cudaGetSymbolAddress((void**)&cs,   g_cs);
    cudaGetSymbolAddress((void**)&prev, g_prev);
    cudaGetSymbolAddress((void**)&ut,   g_ut);
    cudaGetSymbolAddress((void**)&wit,  g_wit);
    cudaGetSymbolAddress((void**)&wot,  g_wot);

    static bool attr_done = false;
    if (!attr_done) {
        cudaFuncSetAttribute(gemm_tn_f16<true>,  cudaFuncAttributeMaxDynamicSharedMemorySize, GSMEM);
        cudaFuncSetAttribute(gemm_tn_f16<false>, cudaFuncAttributeMaxDynamicSharedMemorySize, GSMEM);
        cudaFuncSetAttribute(ssd_chunk_kernel, cudaFuncAttributeMaxDynamicSharedMemorySize, SSD_SMEM);
        attr_done = true;
    }

    // 0) convert operands to fp16
    {
        size_t n4u = (size_t)ROWS * DMODEL / 4;
        h_convert<<<(unsigned)((n4u + 255) / 256), 256>>>(u, ut, n4u);
        size_t n4w = (size_t)ZXB_LD * DMODEL / 4;
        h_convert<<<(unsigned)((n4w + 255) / 256), 256>>>(W_in, wit, n4w);
        size_t n4o = (size_t)DMODEL * DMODEL / 4;
        h_convert<<<(unsigned)((n4o + 255) / 256), 256>>>(W_out, wot, n4o);
    }
    // 1) split GEMM1: z -> fp32 gz, xBC -> fp16 xbch
    gemm_tn_f16<true><<<dim3(ZXB_LD / 128, ROWS / 128), 256, GSMEM>>>(
        ut, wit, gz, xbch, ROWS, ZXB_LD, DMODEL);
    // 2) fused conv + silu + per-chunk SSD
    ssd_chunk_kernel<<<BATCH * NHEADS * NCHUNK, 256, SSD_SMEM>>>(xbch, conv_w, conv_b, chx, y, cs);
    // 3) inter-chunk scan
    scan_kernel<<<BATCH * NHEADS, 64>>>(cs, A_log, prev);
    // 4) Y_off + gate + rmsnorm
    combine_kernel<<<ROWS, 256>>>(y, gz, chx, prev, rms_w, yn);
    // 5) out = yn @ W_out^T (fp32 out)
    gemm_tn_f16<false><<<dim3(DMODEL / 128, ROWS / 128), 256, GSMEM>>>(
        yn, wot, out, (__half*)nullptr, ROWS, DMODEL, DMODEL);
}

// round 14
// speedup vs baseline: 1.2402x; 1.0402x over previous
#include <cuda_runtime.h>
#include <cuda_fp16.h>
#include <math.h>
#include <stdint.h>

// ---------------- constants ----------------
#define BATCH   2
#define SEQ     4096
#define ROWS    (BATCH*SEQ)        // 8192
#define DMODEL  2048
#define DSTATE  64
#define DHEAD   64
#define NHEADS  32
#define CHUNK   64
#define NCHUNK  (SEQ/CHUNK)        // 64
#define CONVD   6144
#define ZXB_LD  8192               // output cols of GEMM1 (dt cols unused)
#define RMS_EPS 1.1920929e-07f

// ---------------- scratch ----------------
__device__ float  g_z   [(size_t)ROWS * DMODEL];   // z (gate input), fp32
__device__ __half g_xbch[(size_t)ROWS * CONVD];    // xBC pre-conv, fp16
__device__ __half g_ch  [(size_t)ROWS * DMODEL];   // silu(conv(C)) compact, fp16
__device__ __half g_y   [(size_t)ROWS * DMODEL];   // Y_diag, fp16
__device__ __half g_yn  [(size_t)ROWS * DMODEL];   // gated+rmsnormed, fp16
__device__ float  g_cs  [(size_t)BATCH*NHEADS*NCHUNK*DSTATE];
__device__ float  g_prev[(size_t)BATCH*NHEADS*NCHUNK*DSTATE];
__device__ __half g_ut  [(size_t)ROWS * DMODEL];
__device__ __half g_wit [(size_t)ZXB_LD * DMODEL];
__device__ __half g_wot [(size_t)DMODEL * DMODEL];

// ---------------- helpers ----------------
__device__ __forceinline__ void cp16(void* dst, const void* src) {
    unsigned saddr = (unsigned)__cvta_generic_to_shared(dst);
    asm volatile("cp.async.cg.shared.global [%0], [%1], 16;" :: "r"(saddr), "l"(src));
}
// fast silu: MUFU.EX2-based exp + MUFU.RCP-based divide (~1e-6 rel err,
// negligible vs the 5e-4 fp16 rounding floor)
__device__ __forceinline__ float silu(float v) {
    return __fdividef(v, 1.f + __expf(-v));
}

__global__ void h_convert(const float* __restrict__ in, __half* __restrict__ out, size_t n4)
{
    size_t i = (size_t)blockIdx.x * blockDim.x + threadIdx.x;
    if (i >= n4) return;
    float4 v = ((const float4*)in)[i];
    __half2 lo = __floats2half2_rn(v.x, v.y);
    __half2 hi = __floats2half2_rn(v.z, v.w);
    uint2 o;
    o.x = *(unsigned*)&lo;
    o.y = *(unsigned*)&hi;
    ((uint2*)out)[i] = o;
}

// ============================================================================
// GEMM (proven config): C[M,N] = A[M,K] * B[N,K]^T ; fp16 in, fp32 acc.
// Block 128x128, warp tile 64x32 (8 warps 2x4), K-tile 64, SW128 swizzle,
// m16n8k16, 3-stage cp.async ring, one sync per K-tile, 2 CTAs/SM.
// SPLIT=true: cols <2048 -> fp32 Cz[ROWS,2048]; cols >=2048 -> fp16
// Ch[ROWS,CONVD] at col-2048 (GEMM1). SPLIT=false: plain fp32 Cz (GEMM2/out).
// ============================================================================
#define NSTG  3
#define KT    64
#define ASZ   (128 * 32)
#define STG   (2 * ASZ)
#define GSMEM (NSTG * STG * 4)      // 98304 B

template<bool SPLIT>
__global__ __launch_bounds__(256, 2) void gemm_tn_f16(
    const __half* __restrict__ A, const __half* __restrict__ B,
    float* __restrict__ Cz, __half* __restrict__ Ch, int M, int N, int K)
{
    extern __shared__ __align__(16) unsigned sm[];

    const int tid  = threadIdx.x;
    const int row0 = blockIdx.y * 128;
    const int col0 = blockIdx.x * 128;
    const int warp = tid >> 5, lane = tid & 31;
    const int wm = warp >> 2, wn = warp & 3;

    float acc[4][4][4];
#pragma unroll
    for (int i = 0; i < 4; i++)
#pragma unroll
        for (int j = 0; j < 4; j++)
#pragma unroll
            for (int k = 0; k < 4; k++) acc[i][j][k] = 0.f;

    const __half* Ag = A + (size_t)row0 * K;
    const __half* Bg = B + (size_t)col0 * K;
    const int NT = K / KT;

    auto issue = [&](int j) {
        unsigned* as = sm + (j % NSTG) * STG;
        unsigned* bs = as + ASZ;
        int k0 = j * KT;
#pragma unroll
        for (int i = 0; i < 4; i++) {
            int ch = tid + i * 256;
            int r = ch >> 3, c = ch & 7;
            cp16(&as[r * 32 + ((c ^ (r & 7)) << 2)], Ag + (size_t)r * K + k0 + c * 8);
        }
#pragma unroll
        for (int i = 0; i < 4; i++) {
            int ch = tid + i * 256;
            int r = ch >> 3, c = ch & 7;
            cp16(&bs[r * 32 + ((c ^ (r & 7)) << 2)], Bg + (size_t)r * K + k0 + c * 8);
        }
        asm volatile("cp.async.commit_group;");
    };

    issue(0);
    if (NT > 1) issue(1);

    const unsigned smb = (unsigned)__cvta_generic_to_shared(sm);
    const int arow = wm * 64 + (lane & 15);
    const int acs  = lane >> 4;
    const int brow = wn * 32 + (lane & 7);
    const int bcs  = (lane >> 3) & 1;

    for (int t = 0; t < NT; t++) {
        if (t + 1 < NT) {
            asm volatile("cp.async.wait_group 1;");
        } else {
            asm volatile("cp.async.wait_group 0;");
        }
        __syncthreads();
        if (t + 2 < NT) issue(t + 2);

        const unsigned sb = smb + (unsigned)(t % NSTG) * (STG * 4);

#pragma unroll
        for (int ks = 0; ks < 4; ks++) {
            unsigned a[4][4], bf[4][2];
#pragma unroll
            for (int mt = 0; mt < 4; mt++) {
                int r = arow + mt * 16;
                unsigned ad = sb + (unsigned)(r * 128 + (((2 * ks + acs) ^ (r & 7)) << 4));
                asm volatile(
                    "ldmatrix.sync.aligned.m8n8.x4.shared.b16 {%0,%1,%2,%3}, [%4];"
                    : "=r"(a[mt][0]), "=r"(a[mt][1]), "=r"(a[mt][2]), "=r"(a[mt][3])
                    : "r"(ad));
            }
#pragma unroll
            for (int nt = 0; nt < 4; nt++) {
                int r = brow + nt * 8;
                unsigned bd = sb + (unsigned)(ASZ * 4) +
                              (unsigned)(r * 128 + (((2 * ks + bcs) ^ (r & 7)) << 4));
                asm volatile(
                    "ldmatrix.sync.aligned.m8n8.x2.shared.b16 {%0,%1}, [%2];"
                    : "=r"(bf[nt][0]), "=r"(bf[nt][1])
                    : "r"(bd));
            }
#pragma unroll
            for (int mt = 0; mt < 4; mt++)
#pragma unroll
                for (int nt = 0; nt < 4; nt++)
                    asm volatile(
                        "mma.sync.aligned.m16n8k16.row.col.f32.f16.f16.f32 "
                        "{%0,%1,%2,%3}, {%4,%5,%6,%7}, {%8,%9}, {%0,%1,%2,%3};"
                        : "+f"(acc[mt][nt][0]), "+f"(acc[mt][nt][1]),
                          "+f"(acc[mt][nt][2]), "+f"(acc[mt][nt][3])
                        : "r"(a[mt][0]), "r"(a[mt][1]), "r"(a[mt][2]), "r"(a[mt][3]),
                          "r"(bf[nt][0]), "r"(bf[nt][1]));
        }
    }

    const int gg = lane >> 2, tt = lane & 3;
    if (!SPLIT) {
#pragma unroll
        for (int mt = 0; mt < 4; mt++) {
            int r = row0 + wm * 64 + mt * 16 + gg;
#pragma unroll
            for (int nt = 0; nt < 4; nt++) {
                int cc = col0 + wn * 32 + nt * 8 + 2 * tt;
                *(float2*)&Cz[(size_t)r * N + cc]       = make_float2(acc[mt][nt][0], acc[mt][nt][1]);
                *(float2*)&Cz[(size_t)(r + 8) * N + cc] = make_float2(acc[mt][nt][2], acc[mt][nt][3]);
            }
        }
    } else if (col0 < DMODEL) {
#pragma unroll
        for (int mt = 0; mt < 4; mt++) {
            int r = row0 + wm * 64 + mt * 16 + gg;
#pragma unroll
            for (int nt = 0; nt < 4; nt++) {
                int cc = col0 + wn * 32 + nt * 8 + 2 * tt;
                *(float2*)&Cz[(size_t)r * DMODEL + cc]       = make_float2(acc[mt][nt][0], acc[mt][nt][1]);
                *(float2*)&Cz[(size_t)(r + 8) * DMODEL + cc] = make_float2(acc[mt][nt][2], acc[mt][nt][3]);
            }
        }
    } else {
#pragma unroll
        for (int mt = 0; mt < 4; mt++) {
            int r = row0 + wm * 64 + mt * 16 + gg;
#pragma unroll
            for (int nt = 0; nt < 4; nt++) {
                int cc = col0 - DMODEL + wn * 32 + nt * 8 + 2 * tt;
                __half2 h0 = __floats2half2_rn(acc[mt][nt][0], acc[mt][nt][1]);
                __half2 h1 = __floats2half2_rn(acc[mt][nt][2], acc[mt][nt][3]);
                *(__half2*)&Ch[(size_t)r * CONVD + cc]       = h0;
                *(__half2*)&Ch[(size_t)(r + 8) * CONVD + cc] = h1;
            }
        }
    }
}

// ============================================================================
// Fused conv+SiLU+SSD. fp16 xBC in; conv fp32; G via fp16 MMA (causal mask
// in epilogue); Y phase fp32; ydiag + compact C out fp16; chunk state fp32.
// ============================================================================
#define SPAD 68
#define TSZ  (64 * SPAD)
#define H16_OFF (3 * TSZ)
#define SSD_SMEM ((3 * TSZ + 4096) * 4)    // 68608 B

__global__ __launch_bounds__(256, 2) void ssd_chunk_kernel(
    const __half* __restrict__ xbch, const float* __restrict__ cw,
    const float* __restrict__ cb,    __half* __restrict__ chx,
    __half* __restrict__ ydiag,      float* __restrict__ cs)
{
    extern __shared__ float ssm[];
    float* Xs = ssm;
    float* Bs = ssm + TSZ;
    float* Gs = ssm + 2 * TSZ;
    char*  CsH = (char*)(ssm + H16_OFF);   // SW128 swizzled fp16 C
    char*  BsH = CsH + 8192;               // SW128 swizzled fp16 B

    int bid = blockIdx.x;
    int c  = bid & 63;
    int bh = bid >> 6;
    int h  = bh & 31;
    int b  = bh >> 5;
    int sl0 = c * CHUNK;
    size_t rbase = (size_t)b * SEQ + sl0;
    int tid = threadIdx.x;

    // ---- conv + silu for x, B, C (fp16 input) ----
#pragma unroll
    for (int reg = 0; reg < 3; reg++) {
        int chbase = reg * 2048 + h * 64;
        for (int i = tid; i < 64 * 16; i += 256) {
            int l = i >> 4, q = (i & 15) * 4;
            size_t r = rbase + l;
            int sl = sl0 + l;
            const __half* p = xbch + r * CONVD + chbase + q;
            uint2 u0 = *(const uint2*)p;
            uint2 um = (sl > 0)       ? *(const uint2*)(p - CONVD) : make_uint2(0u, 0u);
            uint2 up = (sl < SEQ - 1) ? *(const uint2*)(p + CONVD) : make_uint2(0u, 0u);
            __half2 h0a = *(__half2*)&u0.x, h0b = *(__half2*)&u0.y;
            __half2 hma = *(__half2*)&um.x, hmb = *(__half2*)&um.y;
            __half2 hpa = *(__half2*)&up.x, hpb = *(__half2*)&up.y;
            float4 x0 = make_float4(__low2float(h0a), __high2float(h0a),
                                    __low2float(h0b), __high2float(h0b));
            float4 xm = make_float4(__low2float(hma), __high2float(hma),
                                    __low2float(hmb), __high2float(hmb));
            float4 xp = make_float4(__low2float(hpa), __high2float(hpa),
                                    __low2float(hpb), __high2float(hpb));
            int ch = chbase + q;
            float4 v;
            v.x = fmaf(cw[3*ch+0], xm.x, fmaf(cw[3*ch+1], x0.x, fmaf(cw[3*ch+2], xp.x, cb[ch])));
            v.y = fmaf(cw[3*ch+3], xm.y, fmaf(cw[3*ch+4], x0.y, fmaf(cw[3*ch+5], xp.y, cb[ch+1])));
            v.z = fmaf(cw[3*ch+6], xm.z, fmaf(cw[3*ch+7], x0.z, fmaf(cw[3*ch+8], xp.z, cb[ch+2])));
            v.w = fmaf(cw[3*ch+9], xm.w, fmaf(cw[3*ch+10], x0.w, fmaf(cw[3*ch+11], xp.w, cb[ch+3])));
            v.x = silu(v.x); v.y = silu(v.y); v.z = silu(v.z); v.w = silu(v.w);

            if (reg == 0) {
                *(float4*)&Xs[l * SPAD + q] = v;
            } else {
                __half2 lo = __floats2half2_rn(v.x, v.y);
                __half2 hi = __floats2half2_rn(v.z, v.w);
                uint2 hv;
                hv.x = *(unsigned*)&lo;
                hv.y = *(unsigned*)&hi;
                int cc2 = q >> 3;
                int off = (q & 4) << 1;
                int addr = l * 128 + ((cc2 ^ (l & 7)) << 4) + off;
                if (reg == 1) {
                    *(float4*)&Bs[l * SPAD + q] = v;
                    *(uint2*)(BsH + addr) = hv;
                } else {
                    *(uint2*)(CsH + addr) = hv;
                    *(uint2*)&chx[r * DMODEL + h * 64 + q] = hv;
                }
            }
        }
    }
    __syncthreads();

    // ---- G = C . B^T via fp16 MMA; causal mask in epilogue ----
    {
        const int wid  = tid >> 5, lane = tid & 31;
        const int wrow = (wid & 3) * 16;
        const int wcol = (wid >> 2) * 32;
        const unsigned cBase = (unsigned)__cvta_generic_to_shared(CsH);
        const unsigned bBase = (unsigned)__cvta_generic_to_shared(BsH);
        const int ar = wrow + (lane & 15);
        const int acsl = lane >> 4;
        const int br0 = wcol + (lane & 7);
        const int bcsl = (lane >> 3) & 1;

        float acc[4][4];
#pragma unroll
        for (int i = 0; i < 4; i++)
#pragma unroll
            for (int j = 0; j < 4; j++) acc[i][j] = 0.f;

#pragma unroll
        for (int ks = 0; ks < 4; ks++) {
            unsigned a[4];
            unsigned ad = cBase + (unsigned)(ar * 128 + (((2 * ks + acsl) ^ (ar & 7)) << 4));
            asm volatile(
                "ldmatrix.sync.aligned.m8n8.x4.shared.b16 {%0,%1,%2,%3}, [%4];"
                : "=r"(a[0]), "=r"(a[1]), "=r"(a[2]), "=r"(a[3]) : "r"(ad));
#pragma unroll
            for (int nt = 0; nt < 4; nt++) {
                int rr = br0 + nt * 8;
                unsigned bd = bBase + (unsigned)(rr * 128 + (((2 * ks + bcsl) ^ (rr & 7)) << 4));
                unsigned bf0, bf1;
                asm volatile(
                    "ldmatrix.sync.aligned.m8n8.x2.shared.b16 {%0,%1}, [%2];"
                    : "=r"(bf0), "=r"(bf1) : "r"(bd));
                asm volatile(
                    "mma.sync.aligned.m16n8k16.row.col.f32.f16.f16.f32 "
                    "{%0,%1,%2,%3}, {%4,%5,%6,%7}, {%8,%9}, {%0,%1,%2,%3};"
                    : "+f"(acc[nt][0]), "+f"(acc[nt][1]), "+f"(acc[nt][2]), "+f"(acc[nt][3])
                    : "r"(a[0]), "r"(a[1]), "r"(a[2]), "r"(a[3]), "r"(bf0), "r"(bf1));
            }
        }
        const int g = lane >> 2, t4 = lane & 3;
        int r0 = wrow + g, r1 = r0 + 8;
#pragma unroll
        for (int nt = 0; nt < 4; nt++) {
            int c0 = wcol + nt * 8 + 2 * t4, c1 = c0 + 1;
            Gs[r0 * SPAD + c0] = (r0 >= c0) ? acc[nt][0] : 0.f;
            Gs[r0 * SPAD + c1] = (r0 >= c1) ? acc[nt][1] : 0.f;
            Gs[r1 * SPAD + c0] = (r1 >= c0) ? acc[nt][2] : 0.f;
            Gs[r1 * SPAD + c1] = (r1 >= c1) ? acc[nt][3] : 0.f;
        }
    }
    __syncthreads();

    // ---- Y[l][p] = sum_m G[l][m] x[m][p] ; 2 rows x 8 cols per thread ----
    {
        const int lt = tid & 31;
        const int qt = tid >> 5;
        float4 a00 = make_float4(0.f,0.f,0.f,0.f), a01 = a00;
        float4 a10 = a00, a11 = a00;
        const float* gr0 = &Gs[lt * SPAD];
        const float* gr1 = &Gs[(lt + 32) * SPAD];
#pragma unroll 4
        for (int m = 0; m < 64; m++) {
            const float* xr = &Xs[m * SPAD + qt * 8];
            float4 x0 = *(const float4*)&xr[0];
            float4 x1 = *(const float4*)&xr[4];
            float g0 = gr0[m], g1 = gr1[m];
            a00.x = fmaf(g0, x0.x, a00.x); a00.y = fmaf(g0, x0.y, a00.y);
            a00.z = fmaf(g0, x0.z, a00.z); a00.w = fmaf(g0, x0.w, a00.w);
            a01.x = fmaf(g0, x1.x, a01.x); a01.y = fmaf(g0, x1.y, a01.y);
            a01.z = fmaf(g0, x1.z, a01.z); a01.w = fmaf(g0, x1.w, a01.w);
            a10.x = fmaf(g1, x0.x, a10.x); a10.y = fmaf(g1, x0.y, a10.y);
            a10.z = fmaf(g1, x0.z, a10.z); a10.w = fmaf(g1, x0.w, a10.w);
            a11.x = fmaf(g1, x1.x, a11.x); a11.y = fmaf(g1, x1.y, a11.y);
            a11.z = fmaf(g1, x1.z, a11.z); a11.w = fmaf(g1, x1.w, a11.w);
        }
        __half2 p0 = __floats2half2_rn(a00.x, a00.y);
        __half2 p1 = __floats2half2_rn(a00.z, a00.w);
        __half2 p2 = __floats2half2_rn(a01.x, a01.y);
        __half2 p3 = __floats2half2_rn(a01.z, a01.w);
        uint2 w0 = make_uint2(*(unsigned*)&p0, *(unsigned*)&p1);
        uint2 w1 = make_uint2(*(unsigned*)&p2, *(unsigned*)&p3);
        __half2 q0 = __floats2half2_rn(a10.x, a10.y);
        __half2 q1 = __floats2half2_rn(a10.z, a10.w);
        __half2 q2 = __floats2half2_rn(a11.x, a11.y);
        __half2 q3 = __floats2half2_rn(a11.z, a11.w);
        uint2 w2 = make_uint2(*(unsigned*)&q0, *(unsigned*)&q1);
        uint2 w3 = make_uint2(*(unsigned*)&q2, *(unsigned*)&q3);
        __half* yr0 = &ydiag[(rbase + lt) * DMODEL + h * 64 + qt * 8];
        __half* yr1 = &ydiag[(rbase + lt + 32) * DMODEL + h * 64 + qt * 8];
        *(uint2*)&yr0[0] = w0;
        *(uint2*)&yr0[4] = w1;
        *(uint2*)&yr1[0] = w2;
        *(uint2*)&yr1[4] = w3;
    }

    // ---- chunk state (fp32) ----
    if (tid < 64) {
        float a = 0.f;
#pragma unroll 8
        for (int ll = 0; ll < 64; ll++)
            a = fmaf(Xs[ll * SPAD + tid], Bs[ll * SPAD + tid], a);
        cs[(size_t)bid * 64 + tid] = a;
    }
}

// ============================================================================
// Inter-chunk scan (constant decay __expf(63*A_log[h]) per head)
// ============================================================================
__global__ void scan_kernel(const float* __restrict__ cs, const float* __restrict__ A_log,
                            float* __restrict__ prev)
{
    int bh = blockIdx.x;
    int h  = bh & 31;
    int n  = threadIdx.x;
    float d = __expf(63.f * A_log[h]);
    float s = 0.f;
    for (int c = 0; c < NCHUNK; c++) {
        size_t idx = ((size_t)bh * NCHUNK + c) * 64 + n;
        prev[idx] = s;
        s = s * d + cs[idx];
    }
}

// ============================================================================
// Y = Y_diag + Y_off; gate with silu(z); RMSNorm. fp16 inputs, fp32 math.
// ============================================================================
__global__ __launch_bounds__(256) void combine_kernel(
    const __half* __restrict__ ydiag, const float* __restrict__ gz,
    const __half* __restrict__ chx,   const float* __restrict__ prev,
    const float* __restrict__ rms_w,  __half* __restrict__ yn)
{
    int r = blockIdx.x;
    int b = r >> 12;
    int l = r & (SEQ - 1);
    int c = l >> 6;

    __shared__ float sh_yoff[NHEADS];
    __shared__ float sh_red[8];

    int tid = threadIdx.x, warp = tid >> 5, lane = tid & 31;

    for (int h = warp; h < NHEADS; h += 8) {
        const __half* Crow = chx + (size_t)r * DMODEL + h * 64;
        const float* pv    = prev + ((size_t)(b * NHEADS + h) * NCHUNK + c) * 64;
        int n0 = lane * 2;
        float v = __half2float(Crow[n0]) * pv[n0] + __half2float(Crow[n0 + 1]) * pv[n0 + 1];
#pragma unroll
        for (int o = 16; o; o >>= 1) v += __shfl_down_sync(0xffffffffu, v, o);
        if (lane == 0) sh_yoff[h] = v;
    }
    __syncthreads();

    float vals[8];
    float ss = 0.f;
#pragma unroll
    for (int j = 0; j < 8; j++) {
        int d = tid + j * 256;
        float z  = gz[(size_t)r * DMODEL + d];
        float sz = silu(z);
        float y  = (__half2float(ydiag[(size_t)r * DMODEL + d]) + sh_yoff[d >> 6]) * sz;
        vals[j] = y;
        ss += y * y;
    }
#pragma unroll
    for (int o = 16; o; o >>= 1) ss += __shfl_down_sync(0xffffffffu, ss, o);
    if (lane == 0) sh_red[warp] = ss;
    __syncthreads();
    if (tid == 0) {
        float t = 0.f;
#pragma unroll
        for (int w = 0; w < 8; w++) t += sh_red[w];
        sh_red[0] = rsqrtf(t / (float)DMODEL + RMS_EPS);
    }
    __syncthreads();
    float scale = sh_red[0];
#pragma unroll
    for (int j = 0; j < 8; j++) {
        int d = tid + j * 256;
        yn[(size_t)r * DMODEL + d] = __float2half_rn(vals[j] * scale * rms_w[d]);
    }
}

// ============================================================================
// launch
// ============================================================================
extern "C" void kernel_launch(void* const* d_in, const int* in_sizes, int n_in,
                              void* d_out, int out_size)
{
    const float* u      = (const float*)d_in[0];
    const float* W_in   = (const float*)d_in[1];
    const float* W_out  = (const float*)d_in[2];
    const float* conv_w = (const float*)d_in[3];
    const float* conv_b = (const float*)d_in[4];
    const float* A_log  = (const float*)d_in[5];
    const float* rms_w  = (const float*)d_in[6];
    float* out = (float*)d_out;

    float *gz, *cs, *prev;
    __half *xbch, *chx, *y, *yn, *ut, *wit, *wot;
    cudaGetSymbolAddress((void**)&gz,   g_z);
    cudaGetSymbolAddress((void**)&xbch, g_xbch);
    cudaGetSymbolAddress((void**)&chx,  g_ch);
    cudaGetSymbolAddress((void**)&y,    g_y);
    cudaGetSymbolAddress((void**)&yn,   g_yn);
    cudaGetSymbolAddress((void**)&cs,   g_cs);
    cudaGetSymbolAddress((void**)&prev, g_prev);
    cudaGetSymbolAddress((void**)&ut,   g_ut);
    cudaGetSymbolAddress((void**)&wit,  g_wit);
    cudaGetSymbolAddress((void**)&wot,  g_wot);

    static bool attr_done = false;
    if (!attr_done) {
        cudaFuncSetAttribute(gemm_tn_f16<true>,  cudaFuncAttributeMaxDynamicSharedMemorySize, GSMEM);
        cudaFuncSetAttribute(gemm_tn_f16<false>, cudaFuncAttributeMaxDynamicSharedMemorySize, GSMEM);
        cudaFuncSetAttribute(ssd_chunk_kernel, cudaFuncAttributeMaxDynamicSharedMemorySize, SSD_SMEM);
        attr_done = true;
    }

    // 0) convert operands to fp16
    {
        size_t n4u = (size_t)ROWS * DMODEL / 4;
        h_convert<<<(unsigned)((n4u + 255) / 256), 256>>>(u, ut, n4u);
        size_t n4w = (size_t)ZXB_LD * DMODEL / 4;
        h_convert<<<(unsigned)((n4w + 255) / 256), 256>>>(W_in, wit, n4w);
        size_t n4o = (size_t)DMODEL * DMODEL / 4;
        h_convert<<<(unsigned)((n4o + 255) / 256), 256>>>(W_out, wot, n4o);
    }
    // 1) split GEMM1: z -> fp32 gz, xBC -> fp16 xbch
    gemm_tn_f16<true><<<dim3(ZXB_LD / 128, ROWS / 128), 256, GSMEM>>>(
        ut, wit, gz, xbch, ROWS, ZXB_LD, DMODEL);
    // 2) fused conv + silu + per-chunk SSD
    ssd_chunk_kernel<<<BATCH * NHEADS * NCHUNK, 256, SSD_SMEM>>>(xbch, conv_w, conv_b, chx, y, cs);
    // 3) inter-chunk scan
    scan_kernel<<<BATCH * NHEADS, 64>>>(cs, A_log, prev);
    // 4) Y_off + gate + rmsnorm
    combine_kernel<<<ROWS, 256>>>(y, gz, chx, prev, rms_w, yn);
    // 5) out = yn @ W_out^T (fp32 out)
    gemm_tn_f16<false><<<dim3(DMODEL / 128, ROWS / 128), 256, GSMEM>>>(
        yn, wot, out, (__half*)nullptr, ROWS, DMODEL, DMODEL);
}

// round 15
// speedup vs baseline: 1.2588x; 1.0150x over previous
#include <cuda_runtime.h>
#include <cuda_fp16.h>
#include <math.h>
#include <stdint.h>

// ---------------- constants ----------------
#define BATCH   2
#define SEQ     4096
#define ROWS    (BATCH*SEQ)        // 8192
#define DMODEL  2048
#define DSTATE  64
#define DHEAD   64
#define NHEADS  32
#define CHUNK   64
#define NCHUNK  (SEQ/CHUNK)        // 64
#define CONVD   6144
#define ZXB_LD  8192               // output cols of GEMM1 (dt cols unused)
#define RMS_EPS 1.1920929e-07f

// ---------------- scratch ----------------
__device__ float  g_z   [(size_t)ROWS * DMODEL];   // z (gate input), fp32
__device__ __half g_xbch[(size_t)ROWS * CONVD];    // xBC pre-conv, fp16
__device__ __half g_ch  [(size_t)ROWS * DMODEL];   // silu(conv(C)) compact, fp16
__device__ __half g_y   [(size_t)ROWS * DMODEL];   // Y_diag, fp16
__device__ __half g_yn  [(size_t)ROWS * DMODEL];   // gated+rmsnormed, fp16
__device__ float  g_cs  [(size_t)BATCH*NHEADS*NCHUNK*DSTATE];
__device__ float  g_prev[(size_t)BATCH*NHEADS*NCHUNK*DSTATE];
__device__ __half g_ut  [(size_t)ROWS * DMODEL];
__device__ __half g_wit [(size_t)ZXB_LD * DMODEL];
__device__ __half g_wot [(size_t)DMODEL * DMODEL];

// ---------------- helpers ----------------
__device__ __forceinline__ void cp16(void* dst, const void* src) {
    unsigned saddr = (unsigned)__cvta_generic_to_shared(dst);
    asm volatile("cp.async.cg.shared.global [%0], [%1], 16;" :: "r"(saddr), "l"(src));
}
__device__ __forceinline__ void sts_zero16(void* dst) {
    unsigned saddr = (unsigned)__cvta_generic_to_shared(dst);
    asm volatile("st.shared.v4.u32 [%0], {%1,%1,%1,%1};" :: "r"(saddr), "r"(0u));
}
__device__ __forceinline__ float silu(float v) {
    return __fdividef(v, 1.f + __expf(-v));
}

__global__ void h_convert(const float* __restrict__ in, __half* __restrict__ out, size_t n4)
{
    size_t i = (size_t)blockIdx.x * blockDim.x + threadIdx.x;
    if (i >= n4) return;
    float4 v = ((const float4*)in)[i];
    __half2 lo = __floats2half2_rn(v.x, v.y);
    __half2 hi = __floats2half2_rn(v.z, v.w);
    uint2 o;
    o.x = *(unsigned*)&lo;
    o.y = *(unsigned*)&hi;
    ((uint2*)out)[i] = o;
}

// ============================================================================
// GEMM (proven config): C[M,N] = A[M,K] * B[N,K]^T ; fp16 in, fp32 acc.
// Block 128x128, warp tile 64x32, K-tile 64, SW128 swizzle, m16n8k16,
// 3-stage cp.async ring, one sync per K-tile, 2 CTAs/SM.
// ============================================================================
#define NSTG  3
#define KT    64
#define ASZ   (128 * 32)
#define STG   (2 * ASZ)
#define GSMEM (NSTG * STG * 4)      // 98304 B

template<bool SPLIT>
__global__ __launch_bounds__(256, 2) void gemm_tn_f16(
    const __half* __restrict__ A, const __half* __restrict__ B,
    float* __restrict__ Cz, __half* __restrict__ Ch, int M, int N, int K)
{
    extern __shared__ __align__(16) unsigned sm[];

    const int tid  = threadIdx.x;
    const int row0 = blockIdx.y * 128;
    const int col0 = blockIdx.x * 128;
    const int warp = tid >> 5, lane = tid & 31;
    const int wm = warp >> 2, wn = warp & 3;

    float acc[4][4][4];
#pragma unroll
    for (int i = 0; i < 4; i++)
#pragma unroll
        for (int j = 0; j < 4; j++)
#pragma unroll
            for (int k = 0; k < 4; k++) acc[i][j][k] = 0.f;

    const __half* Ag = A + (size_t)row0 * K;
    const __half* Bg = B + (size_t)col0 * K;
    const int NT = K / KT;

    auto issue = [&](int j) {
        unsigned* as = sm + (j % NSTG) * STG;
        unsigned* bs = as + ASZ;
        int k0 = j * KT;
#pragma unroll
        for (int i = 0; i < 4; i++) {
            int ch = tid + i * 256;
            int r = ch >> 3, c = ch & 7;
            cp16(&as[r * 32 + ((c ^ (r & 7)) << 2)], Ag + (size_t)r * K + k0 + c * 8);
        }
#pragma unroll
        for (int i = 0; i < 4; i++) {
            int ch = tid + i * 256;
            int r = ch >> 3, c = ch & 7;
            cp16(&bs[r * 32 + ((c ^ (r & 7)) << 2)], Bg + (size_t)r * K + k0 + c * 8);
        }
        asm volatile("cp.async.commit_group;");
    };

    issue(0);
    if (NT > 1) issue(1);

    const unsigned smb = (unsigned)__cvta_generic_to_shared(sm);
    const int arow = wm * 64 + (lane & 15);
    const int acs  = lane >> 4;
    const int brow = wn * 32 + (lane & 7);
    const int bcs  = (lane >> 3) & 1;

    for (int t = 0; t < NT; t++) {
        if (t + 1 < NT) {
            asm volatile("cp.async.wait_group 1;");
        } else {
            asm volatile("cp.async.wait_group 0;");
        }
        __syncthreads();
        if (t + 2 < NT) issue(t + 2);

        const unsigned sb = smb + (unsigned)(t % NSTG) * (STG * 4);

#pragma unroll
        for (int ks = 0; ks < 4; ks++) {
            unsigned a[4][4], bf[4][2];
#pragma unroll
            for (int mt = 0; mt < 4; mt++) {
                int r = arow + mt * 16;
                unsigned ad = sb + (unsigned)(r * 128 + (((2 * ks + acs) ^ (r & 7)) << 4));
                asm volatile(
                    "ldmatrix.sync.aligned.m8n8.x4.shared.b16 {%0,%1,%2,%3}, [%4];"
                    : "=r"(a[mt][0]), "=r"(a[mt][1]), "=r"(a[mt][2]), "=r"(a[mt][3])
                    : "r"(ad));
            }
#pragma unroll
            for (int nt = 0; nt < 4; nt++) {
                int r = brow + nt * 8;
                unsigned bd = sb + (unsigned)(ASZ * 4) +
                              (unsigned)(r * 128 + (((2 * ks + bcs) ^ (r & 7)) << 4));
                asm volatile(
                    "ldmatrix.sync.aligned.m8n8.x2.shared.b16 {%0,%1}, [%2];"
                    : "=r"(bf[nt][0]), "=r"(bf[nt][1])
                    : "r"(bd));
            }
#pragma unroll
            for (int mt = 0; mt < 4; mt++)
#pragma unroll
                for (int nt = 0; nt < 4; nt++)
                    asm volatile(
                        "mma.sync.aligned.m16n8k16.row.col.f32.f16.f16.f32 "
                        "{%0,%1,%2,%3}, {%4,%5,%6,%7}, {%8,%9}, {%0,%1,%2,%3};"
                        : "+f"(acc[mt][nt][0]), "+f"(acc[mt][nt][1]),
                          "+f"(acc[mt][nt][2]), "+f"(acc[mt][nt][3])
                        : "r"(a[mt][0]), "r"(a[mt][1]), "r"(a[mt][2]), "r"(a[mt][3]),
                          "r"(bf[nt][0]), "r"(bf[nt][1]));
        }
    }

    const int gg = lane >> 2, tt = lane & 3;
    if (!SPLIT) {
#pragma unroll
        for (int mt = 0; mt < 4; mt++) {
            int r = row0 + wm * 64 + mt * 16 + gg;
#pragma unroll
            for (int nt = 0; nt < 4; nt++) {
                int cc = col0 + wn * 32 + nt * 8 + 2 * tt;
                *(float2*)&Cz[(size_t)r * N + cc]       = make_float2(acc[mt][nt][0], acc[mt][nt][1]);
                *(float2*)&Cz[(size_t)(r + 8) * N + cc] = make_float2(acc[mt][nt][2], acc[mt][nt][3]);
            }
        }
    } else if (col0 < DMODEL) {
#pragma unroll
        for (int mt = 0; mt < 4; mt++) {
            int r = row0 + wm * 64 + mt * 16 + gg;
#pragma unroll
            for (int nt = 0; nt < 4; nt++) {
                int cc = col0 + wn * 32 + nt * 8 + 2 * tt;
                *(float2*)&Cz[(size_t)r * DMODEL + cc]       = make_float2(acc[mt][nt][0], acc[mt][nt][1]);
                *(float2*)&Cz[(size_t)(r + 8) * DMODEL + cc] = make_float2(acc[mt][nt][2], acc[mt][nt][3]);
            }
        }
    } else {
#pragma unroll
        for (int mt = 0; mt < 4; mt++) {
            int r = row0 + wm * 64 + mt * 16 + gg;
#pragma unroll
            for (int nt = 0; nt < 4; nt++) {
                int cc = col0 - DMODEL + wn * 32 + nt * 8 + 2 * tt;
                __half2 h0 = __floats2half2_rn(acc[mt][nt][0], acc[mt][nt][1]);
                __half2 h1 = __floats2half2_rn(acc[mt][nt][2], acc[mt][nt][3]);
                *(__half2*)&Ch[(size_t)r * CONVD + cc]       = h0;
                *(__half2*)&Ch[(size_t)(r + 8) * CONVD + cc] = h1;
            }
        }
    }
}

// ============================================================================
// Fused conv+SiLU+SSD. NEW: the 3 fp16 input tiles (66 rows incl. halo) are
// staged into smem once via cp.async (boundary rows zero-filled), so conv
// reads LDS instead of 3x-redundant gmem. Staging buffer aliases Gs (dead by
// the time G is written). G via fp16 MMA; Y phase fp32; outputs fp16.
// ============================================================================
#define SPAD 68
#define TSZ  (64 * SPAD)                   // 4352 floats
#define HST  72                            // staging stride in halves (144B, 16B-mult)
#define RSTG (66 * HST * 2)                // 9504 B per region
// byte layout: Xs@0 (17408) | Bs@17408 (17408) | union{staging(3*9504=28512)|Gs(17408)}@34816
// | CsH@63328 (8192) | BsH@71520 (8192) -> total 79712
#define STAGE_BOFF 34816
#define CSH_BOFF   63328
#define SSD_SMEM   79712

__global__ __launch_bounds__(256, 2) void ssd_chunk_kernel(
    const __half* __restrict__ xbch, const float* __restrict__ cw,
    const float* __restrict__ cb,    __half* __restrict__ chx,
    __half* __restrict__ ydiag,      float* __restrict__ cs)
{
    extern __shared__ float ssm[];
    float* Xs = ssm;
    float* Bs = ssm + TSZ;
    float* Gs = (float*)((char*)ssm + STAGE_BOFF);   // aliases staging
    char*  Hs = (char*)ssm + STAGE_BOFF;             // staging base
    char*  CsH = (char*)ssm + CSH_BOFF;
    char*  BsH = CsH + 8192;

    int bid = blockIdx.x;
    int c  = bid & 63;
    int bh = bid >> 6;
    int h  = bh & 31;
    int b  = bh >> 5;
    int sl0 = c * CHUNK;
    size_t rbase = (size_t)b * SEQ + sl0;
    int tid = threadIdx.x;

    // ---- stage 3 regions x 66 rows (halo +-1) of fp16 input into smem ----
    for (int i = tid; i < 3 * 66 * 8; i += 256) {
        int reg = i / 528;
        int rem = i - reg * 528;
        int row = rem >> 3;          // 0..65
        int ch  = rem & 7;           // 16B chunk
        int sl  = sl0 - 1 + row;
        char* dst = Hs + reg * RSTG + row * (HST * 2) + ch * 16;
        if (sl >= 0 && sl < SEQ) {
            cp16(dst, xbch + ((size_t)b * SEQ + sl) * CONVD + reg * 2048 + h * 64 + ch * 8);
        } else {
            sts_zero16(dst);
        }
    }
    asm volatile("cp.async.commit_group;");
    asm volatile("cp.async.wait_group 0;");
    __syncthreads();

    // ---- conv + silu for x, B, C (reads staged smem) ----
#pragma unroll
    for (int reg = 0; reg < 3; reg++) {
        const char* Hreg = Hs + reg * RSTG;
        int chbase = reg * 2048 + h * 64;
        for (int i = tid; i < 64 * 16; i += 256) {
            int l = i >> 4, q = (i & 15) * 4;
            size_t r = rbase + l;
            const char* rp = Hreg + l * (HST * 2) + q * 2;
            uint2 um = *(const uint2*)(rp);                 // row l   (= sl-1)
            uint2 u0 = *(const uint2*)(rp + HST * 2);       // row l+1 (= sl)
            uint2 up = *(const uint2*)(rp + HST * 4);       // row l+2 (= sl+1)
            __half2 h0a = *(__half2*)&u0.x, h0b = *(__half2*)&u0.y;
            __half2 hma = *(__half2*)&um.x, hmb = *(__half2*)&um.y;
            __half2 hpa = *(__half2*)&up.x, hpb = *(__half2*)&up.y;
            float4 x0 = make_float4(__low2float(h0a), __high2float(h0a),
                                    __low2float(h0b), __high2float(h0b));
            float4 xm = make_float4(__low2float(hma), __high2float(hma),
                                    __low2float(hmb), __high2float(hmb));
            float4 xp = make_float4(__low2float(hpa), __high2float(hpa),
                                    __low2float(hpb), __high2float(hpb));
            int ch = chbase + q;
            float4 v;
            v.x = fmaf(cw[3*ch+0], xm.x, fmaf(cw[3*ch+1], x0.x, fmaf(cw[3*ch+2], xp.x, cb[ch])));
            v.y = fmaf(cw[3*ch+3], xm.y, fmaf(cw[3*ch+4], x0.y, fmaf(cw[3*ch+5], xp.y, cb[ch+1])));
            v.z = fmaf(cw[3*ch+6], xm.z, fmaf(cw[3*ch+7], x0.z, fmaf(cw[3*ch+8], xp.z, cb[ch+2])));
            v.w = fmaf(cw[3*ch+9], xm.w, fmaf(cw[3*ch+10], x0.w, fmaf(cw[3*ch+11], xp.w, cb[ch+3])));
            v.x = silu(v.x); v.y = silu(v.y); v.z = silu(v.z); v.w = silu(v.w);

            if (reg == 0) {
                *(float4*)&Xs[l * SPAD + q] = v;
            } else {
                __half2 lo = __floats2half2_rn(v.x, v.y);
                __half2 hi = __floats2half2_rn(v.z, v.w);
                uint2 hv;
                hv.x = *(unsigned*)&lo;
                hv.y = *(unsigned*)&hi;
                int cc2 = q >> 3;
                int off = (q & 4) << 1;
                int addr = l * 128 + ((cc2 ^ (l & 7)) << 4) + off;
                if (reg == 1) {
                    *(float4*)&Bs[l * SPAD + q] = v;
                    *(uint2*)(BsH + addr) = hv;
                } else {
                    *(uint2*)(CsH + addr) = hv;
                    *(uint2*)&chx[r * DMODEL + h * 64 + q] = hv;
                }
            }
        }
        __syncthreads();   // after reg 2 this also protects Gs-over-staging reuse
    }

    // ---- G = C . B^T via fp16 MMA; causal mask in epilogue (writes Gs,
    //      which aliases the now-dead staging buffer) ----
    {
        const int wid  = tid >> 5, lane = tid & 31;
        const int wrow = (wid & 3) * 16;
        const int wcol = (wid >> 2) * 32;
        const unsigned cBase = (unsigned)__cvta_generic_to_shared(CsH);
        const unsigned bBase = (unsigned)__cvta_generic_to_shared(BsH);
        const int ar = wrow + (lane & 15);
        const int acsl = lane >> 4;
        const int br0 = wcol + (lane & 7);
        const int bcsl = (lane >> 3) & 1;

        float acc[4][4];
#pragma unroll
        for (int i = 0; i < 4; i++)
#pragma unroll
            for (int j = 0; j < 4; j++) acc[i][j] = 0.f;

#pragma unroll
        for (int ks = 0; ks < 4; ks++) {
            unsigned a[4];
            unsigned ad = cBase + (unsigned)(ar * 128 + (((2 * ks + acsl) ^ (ar & 7)) << 4));
            asm volatile(
                "ldmatrix.sync.aligned.m8n8.x4.shared.b16 {%0,%1,%2,%3}, [%4];"
                : "=r"(a[0]), "=r"(a[1]), "=r"(a[2]), "=r"(a[3]) : "r"(ad));
#pragma unroll
            for (int nt = 0; nt < 4; nt++) {
                int rr = br0 + nt * 8;
                unsigned bd = bBase + (unsigned)(rr * 128 + (((2 * ks + bcsl) ^ (rr & 7)) << 4));
                unsigned bf0, bf1;
                asm volatile(
                    "ldmatrix.sync.aligned.m8n8.x2.shared.b16 {%0,%1}, [%2];"
                    : "=r"(bf0), "=r"(bf1) : "r"(bd));
                asm volatile(
                    "mma.sync.aligned.m16n8k16.row.col.f32.f16.f16.f32 "
                    "{%0,%1,%2,%3}, {%4,%5,%6,%7}, {%8,%9}, {%0,%1,%2,%3};"
                    : "+f"(acc[nt][0]), "+f"(acc[nt][1]), "+f"(acc[nt][2]), "+f"(acc[nt][3])
                    : "r"(a[0]), "r"(a[1]), "r"(a[2]), "r"(a[3]), "r"(bf0), "r"(bf1));
            }
        }
        const int g = lane >> 2, t4 = lane & 3;
        int r0 = wrow + g, r1 = r0 + 8;
#pragma unroll
        for (int nt = 0; nt < 4; nt++) {
            int c0 = wcol + nt * 8 + 2 * t4, c1 = c0 + 1;
            Gs[r0 * SPAD + c0] = (r0 >= c0) ? acc[nt][0] : 0.f;
            Gs[r0 * SPAD + c1] = (r0 >= c1) ? acc[nt][1] : 0.f;
            Gs[r1 * SPAD + c0] = (r1 >= c0) ? acc[nt][2] : 0.f;
            Gs[r1 * SPAD + c1] = (r1 >= c1) ? acc[nt][3] : 0.f;
        }
    }
    __syncthreads();

    // ---- Y[l][p] = sum_m G[l][m] x[m][p] ; 2 rows x 8 cols per thread ----
    {
        const int lt = tid & 31;
        const int qt = tid >> 5;
        float4 a00 = make_float4(0.f,0.f,0.f,0.f), a01 = a00;
        float4 a10 = a00, a11 = a00;
        const float* gr0 = &Gs[lt * SPAD];
        const float* gr1 = &Gs[(lt + 32) * SPAD];
#pragma unroll 4
        for (int m = 0; m < 64; m++) {
            const float* xr = &Xs[m * SPAD + qt * 8];
            float4 x0 = *(const float4*)&xr[0];
            float4 x1 = *(const float4*)&xr[4];
            float g0 = gr0[m], g1 = gr1[m];
            a00.x = fmaf(g0, x0.x, a00.x); a00.y = fmaf(g0, x0.y, a00.y);
            a00.z = fmaf(g0, x0.z, a00.z); a00.w = fmaf(g0, x0.w, a00.w);
            a01.x = fmaf(g0, x1.x, a01.x); a01.y = fmaf(g0, x1.y, a01.y);
            a01.z = fmaf(g0, x1.z, a01.z); a01.w = fmaf(g0, x1.w, a01.w);
            a10.x = fmaf(g1, x0.x, a10.x); a10.y = fmaf(g1, x0.y, a10.y);
            a10.z = fmaf(g1, x0.z, a10.z); a10.w = fmaf(g1, x0.w, a10.w);
            a11.x = fmaf(g1, x1.x, a11.x); a11.y = fmaf(g1, x1.y, a11.y);
            a11.z = fmaf(g1, x1.z, a11.z); a11.w = fmaf(g1, x1.w, a11.w);
        }
        __half2 p0 = __floats2half2_rn(a00.x, a00.y);
        __half2 p1 = __floats2half2_rn(a00.z, a00.w);
        __half2 p2 = __floats2half2_rn(a01.x, a01.y);
        __half2 p3 = __floats2half2_rn(a01.z, a01.w);
        uint2 w0 = make_uint2(*(unsigned*)&p0, *(unsigned*)&p1);
        uint2 w1 = make_uint2(*(unsigned*)&p2, *(unsigned*)&p3);
        __half2 q0 = __floats2half2_rn(a10.x, a10.y);
        __half2 q1 = __floats2half2_rn(a10.z, a10.w);
        __half2 q2 = __floats2half2_rn(a11.x, a11.y);
        __half2 q3 = __floats2half2_rn(a11.z, a11.w);
        uint2 w2 = make_uint2(*(unsigned*)&q0, *(unsigned*)&q1);
        uint2 w3 = make_uint2(*(unsigned*)&q2, *(unsigned*)&q3);
        __half* yr0 = &ydiag[(rbase + lt) * DMODEL + h * 64 + qt * 8];
        __half* yr1 = &ydiag[(rbase + lt + 32) * DMODEL + h * 64 + qt * 8];
        *(uint2*)&yr0[0] = w0;
        *(uint2*)&yr0[4] = w1;
        *(uint2*)&yr1[0] = w2;
        *(uint2*)&yr1[4] = w3;
    }

    // ---- chunk state (fp32) ----
    if (tid < 64) {
        float a = 0.f;
#pragma unroll 8
        for (int ll = 0; ll < 64; ll++)
            a = fmaf(Xs[ll * SPAD + tid], Bs[ll * SPAD + tid], a);
        cs[(size_t)bid * 64 + tid] = a;
    }
}

// ============================================================================
// Inter-chunk scan
// ============================================================================
__global__ void scan_kernel(const float* __restrict__ cs, const float* __restrict__ A_log,
                            float* __restrict__ prev)
{
    int bh = blockIdx.x;
    int h  = bh & 31;
    int n  = threadIdx.x;
    float d = __expf(63.f * A_log[h]);
    float s = 0.f;
    for (int c = 0; c < NCHUNK; c++) {
        size_t idx = ((size_t)bh * NCHUNK + c) * 64 + n;
        prev[idx] = s;
        s = s * d + cs[idx];
    }
}

// ============================================================================
// Y = Y_diag + Y_off; gate silu(z); RMSNorm. Vectorized: 8 consecutive cols
// per thread (single head -> one yoff), 128-bit loads/stores.
// ============================================================================
__global__ __launch_bounds__(256) void combine_kernel(
    const __half* __restrict__ ydiag, const float* __restrict__ gz,
    const __half* __restrict__ chx,   const float* __restrict__ prev,
    const float* __restrict__ rms_w,  __half* __restrict__ yn)
{
    int r = blockIdx.x;
    int b = r >> 12;
    int l = r & (SEQ - 1);
    int c = l >> 6;

    __shared__ float sh_yoff[NHEADS];
    __shared__ float sh_red[8];

    int tid = threadIdx.x, warp = tid >> 5, lane = tid & 31;

    for (int h = warp; h < NHEADS; h += 8) {
        const __half* Crow = chx + (size_t)r * DMODEL + h * 64;
        const float* pv    = prev + ((size_t)(b * NHEADS + h) * NCHUNK + c) * 64;
        int n0 = lane * 2;
        float v = __half2float(Crow[n0]) * pv[n0] + __half2float(Crow[n0 + 1]) * pv[n0 + 1];
#pragma unroll
        for (int o = 16; o; o >>= 1) v += __shfl_down_sync(0xffffffffu, v, o);
        if (lane == 0) sh_yoff[h] = v;
    }
    __syncthreads();

    const int d0 = tid * 8;
    float4 z0 = *(const float4*)&gz[(size_t)r * DMODEL + d0];
    float4 z1 = *(const float4*)&gz[(size_t)r * DMODEL + d0 + 4];
    uint4 yd  = *(const uint4*)&ydiag[(size_t)r * DMODEL + d0];
    __half2 y01 = *(__half2*)&yd.x, y23 = *(__half2*)&yd.y;
    __half2 y45 = *(__half2*)&yd.z, y67 = *(__half2*)&yd.w;
    float yoff = sh_yoff[d0 >> 6];

    float vals[8];
    vals[0] = (__low2float(y01)  + yoff) * silu(z0.x);
    vals[1] = (__high2float(y01) + yoff) * silu(z0.y);
    vals[2] = (__low2float(y23)  + yoff) * silu(z0.z);
    vals[3] = (__high2float(y23) + yoff) * silu(z0.w);
    vals[4] = (__low2float(y45)  + yoff) * silu(z1.x);
    vals[5] = (__high2float(y45) + yoff) * silu(z1.y);
    vals[6] = (__low2float(y67)  + yoff) * silu(z1.z);
    vals[7] = (__high2float(y67) + yoff) * silu(z1.w);

    float ss = 0.f;
#pragma unroll
    for (int j = 0; j < 8; j++) ss += vals[j] * vals[j];
#pragma unroll
    for (int o = 16; o; o >>= 1) ss += __shfl_down_sync(0xffffffffu, ss, o);
    if (lane == 0) sh_red[warp] = ss;
    __syncthreads();
    if (tid == 0) {
        float t = 0.f;
#pragma unroll
        for (int w = 0; w < 8; w++) t += sh_red[w];
        sh_red[0] = rsqrtf(t / (float)DMODEL + RMS_EPS);
    }
    __syncthreads();
    float scale = sh_red[0];

    float4 rw0 = *(const float4*)&rms_w[d0];
    float4 rw1 = *(const float4*)&rms_w[d0 + 4];
    __half2 o0 = __floats2half2_rn(vals[0] * scale * rw0.x, vals[1] * scale * rw0.y);
    __half2 o1 = __floats2half2_rn(vals[2] * scale * rw0.z, vals[3] * scale * rw0.w);
    __half2 o2 = __floats2half2_rn(vals[4] * scale * rw1.x, vals[5] * scale * rw1.y);
    __half2 o3 = __floats2half2_rn(vals[6] * scale * rw1.z, vals[7] * scale * rw1.w);
    uint4 ov = make_uint4(*(unsigned*)&o0, *(unsigned*)&o1, *(unsigned*)&o2, *(unsigned*)&o3);
    *(uint4*)&yn[(size_t)r * DMODEL + d0] = ov;
}

// ============================================================================
// launch
// ============================================================================
extern "C" void kernel_launch(void* const* d_in, const int* in_sizes, int n_in,
                              void* d_out, int out_size)
{
    const float* u      = (const float*)d_in[0];
    const float* W_in   = (const float*)d_in[1];
    const float* W_out  = (const float*)d_in[2];
    const float* conv_w = (const float*)d_in[3];
    const float* conv_b = (const float*)d_in[4];
    const float* A_log  = (const float*)d_in[5];
    const float* rms_w  = (const float*)d_in[6];
    float* out = (float*)d_out;

    float *gz, *cs, *prev;
    __half *xbch, *chx, *y, *yn, *ut, *wit, *wot;
    cudaGetSymbolAddress((void**)&gz,   g_z);
    cudaGetSymbolAddress((void**)&xbch, g_xbch);
    cudaGetSymbolAddress((void**)&chx,  g_ch);
    cudaGetSymbolAddress((void**)&y,    g_y);
    cudaGetSymbolAddress((void**)&yn,   g_yn);
    cudaGetSymbolAddress((void**)&cs,   g_cs);
    cudaGetSymbolAddress((void**)&prev, g_prev);
    cudaGetSymbolAddress((void**)&ut,   g_ut);
    cudaGetSymbolAddress((void**)&wit,  g_wit);
    cudaGetSymbolAddress((void**)&wot,  g_wot);

    static bool attr_done = false;
    if (!attr_done) {
        cudaFuncSetAttribute(gemm_tn_f16<true>,  cudaFuncAttributeMaxDynamicSharedMemorySize, GSMEM);
        cudaFuncSetAttribute(gemm_tn_f16<false>, cudaFuncAttributeMaxDynamicSharedMemorySize, GSMEM);
        cudaFuncSetAttribute(ssd_chunk_kernel, cudaFuncAttributeMaxDynamicSharedMemorySize, SSD_SMEM);
        attr_done = true;
    }

    // 0) convert operands to fp16
    {
        size_t n4u = (size_t)ROWS * DMODEL / 4;
        h_convert<<<(unsigned)((n4u + 255) / 256), 256>>>(u, ut, n4u);
        size_t n4w = (size_t)ZXB_LD * DMODEL / 4;
        h_convert<<<(unsigned)((n4w + 255) / 256), 256>>>(W_in, wit, n4w);
        size_t n4o = (size_t)DMODEL * DMODEL / 4;
        h_convert<<<(unsigned)((n4o + 255) / 256), 256>>>(W_out, wot, n4o);
    }
    // 1) split GEMM1: z -> fp32 gz, xBC -> fp16 xbch
    gemm_tn_f16<true><<<dim3(ZXB_LD / 128, ROWS / 128), 256, GSMEM>>>(
        ut, wit, gz, xbch, ROWS, ZXB_LD, DMODEL);
    // 2) fused conv + silu + per-chunk SSD (smem-staged halo)
    ssd_chunk_kernel<<<BATCH * NHEADS * NCHUNK, 256, SSD_SMEM>>>(xbch, conv_w, conv_b, chx, y, cs);
    // 3) inter-chunk scan
    scan_kernel<<<BATCH * NHEADS, 64>>>(cs, A_log, prev);
    // 4) Y_off + gate + rmsnorm (vectorized)
    combine_kernel<<<ROWS, 256>>>(y, gz, chx, prev, rms_w, yn);
    // 5) out = yn @ W_out^T (fp32 out)
    gemm_tn_f16<false><<<dim3(DMODEL / 128, ROWS / 128), 256, GSMEM>>>(
        yn, wot, out, (__half*)nullptr, ROWS, DMODEL, DMODEL);
}

// round 16
// speedup vs baseline: 1.3484x; 1.0712x over previous
#include <cuda_runtime.h>
#include <cuda_fp16.h>
#include <math.h>
#include <stdint.h>

// ---------------- constants ----------------
#define BATCH   2
#define SEQ     4096
#define ROWS    (BATCH*SEQ)        // 8192
#define DMODEL  2048
#define DSTATE  64
#define DHEAD   64
#define NHEADS  32
#define CHUNK   64
#define NCHUNK  (SEQ/CHUNK)        // 64
#define CONVD   6144
#define ZXB_LD  8192               // output cols of GEMM1 (dt cols unused)
#define RMS_EPS 1.1920929e-07f

// ---------------- scratch ----------------
__device__ float  g_z   [(size_t)ROWS * DMODEL];   // z (gate input), fp32
__device__ __half g_xbch[(size_t)ROWS * CONVD];    // xBC pre-conv, fp16
__device__ __half g_ch  [(size_t)ROWS * DMODEL];   // silu(conv(C)) compact, fp16
__device__ __half g_y   [(size_t)ROWS * DMODEL];   // Y_diag, fp16
__device__ __half g_yn  [(size_t)ROWS * DMODEL];   // gated+rmsnormed, fp16
__device__ float  g_cs  [(size_t)BATCH*NHEADS*NCHUNK*DSTATE];
__device__ float  g_prev[(size_t)BATCH*NHEADS*NCHUNK*DSTATE];
__device__ __half g_ut  [(size_t)ROWS * DMODEL];
__device__ __half g_wit [(size_t)ZXB_LD * DMODEL];
__device__ __half g_wot [(size_t)DMODEL * DMODEL];

// ---------------- helpers ----------------
__device__ __forceinline__ void cp16(void* dst, const void* src) {
    unsigned saddr = (unsigned)__cvta_generic_to_shared(dst);
    asm volatile("cp.async.cg.shared.global [%0], [%1], 16;" :: "r"(saddr), "l"(src));
}
__device__ __forceinline__ void sts_zero16(void* dst) {
    unsigned saddr = (unsigned)__cvta_generic_to_shared(dst);
    asm volatile("st.shared.v4.u32 [%0], {%1,%1,%1,%1};" :: "r"(saddr), "r"(0u));
}
__device__ __forceinline__ float silu(float v) {
    return __fdividef(v, 1.f + __expf(-v));
}

__global__ void h_convert(const float* __restrict__ in, __half* __restrict__ out, size_t n4)
{
    size_t i = (size_t)blockIdx.x * blockDim.x + threadIdx.x;
    if (i >= n4) return;
    float4 v = ((const float4*)in)[i];
    __half2 lo = __floats2half2_rn(v.x, v.y);
    __half2 hi = __floats2half2_rn(v.z, v.w);
    uint2 o;
    o.x = *(unsigned*)&lo;
    o.y = *(unsigned*)&hi;
    ((uint2*)out)[i] = o;
}

// ============================================================================
// GEMM (proven config): C[M,N] = A[M,K] * B[N,K]^T ; fp16 in, fp32 acc.
// Block 128x128, warp tile 64x32, K-tile 64, SW128 swizzle, m16n8k16,
// 3-stage cp.async ring, one sync per K-tile, 2 CTAs/SM.
// ============================================================================
#define NSTG  3
#define KT    64
#define ASZ   (128 * 32)
#define STG   (2 * ASZ)
#define GSMEM (NSTG * STG * 4)      // 98304 B

template<bool SPLIT>
__global__ __launch_bounds__(256, 2) void gemm_tn_f16(
    const __half* __restrict__ A, const __half* __restrict__ B,
    float* __restrict__ Cz, __half* __restrict__ Ch, int M, int N, int K)
{
    extern __shared__ __align__(16) unsigned sm[];

    const int tid  = threadIdx.x;
    const int row0 = blockIdx.y * 128;
    const int col0 = blockIdx.x * 128;
    const int warp = tid >> 5, lane = tid & 31;
    const int wm = warp >> 2, wn = warp & 3;

    float acc[4][4][4];
#pragma unroll
    for (int i = 0; i < 4; i++)
#pragma unroll
        for (int j = 0; j < 4; j++)
#pragma unroll
            for (int k = 0; k < 4; k++) acc[i][j][k] = 0.f;

    const __half* Ag = A + (size_t)row0 * K;
    const __half* Bg = B + (size_t)col0 * K;
    const int NT = K / KT;

    auto issue = [&](int j) {
        unsigned* as = sm + (j % NSTG) * STG;
        unsigned* bs = as + ASZ;
        int k0 = j * KT;
#pragma unroll
        for (int i = 0; i < 4; i++) {
            int ch = tid + i * 256;
            int r = ch >> 3, c = ch & 7;
            cp16(&as[r * 32 + ((c ^ (r & 7)) << 2)], Ag + (size_t)r * K + k0 + c * 8);
        }
#pragma unroll
        for (int i = 0; i < 4; i++) {
            int ch = tid + i * 256;
            int r = ch >> 3, c = ch & 7;
            cp16(&bs[r * 32 + ((c ^ (r & 7)) << 2)], Bg + (size_t)r * K + k0 + c * 8);
        }
        asm volatile("cp.async.commit_group;");
    };

    issue(0);
    if (NT > 1) issue(1);

    const unsigned smb = (unsigned)__cvta_generic_to_shared(sm);
    const int arow = wm * 64 + (lane & 15);
    const int acs  = lane >> 4;
    const int brow = wn * 32 + (lane & 7);
    const int bcs  = (lane >> 3) & 1;

    for (int t = 0; t < NT; t++) {
        if (t + 1 < NT) {
            asm volatile("cp.async.wait_group 1;");
        } else {
            asm volatile("cp.async.wait_group 0;");
        }
        __syncthreads();
        if (t + 2 < NT) issue(t + 2);

        const unsigned sb = smb + (unsigned)(t % NSTG) * (STG * 4);

#pragma unroll
        for (int ks = 0; ks < 4; ks++) {
            unsigned a[4][4], bf[4][2];
#pragma unroll
            for (int mt = 0; mt < 4; mt++) {
                int r = arow + mt * 16;
                unsigned ad = sb + (unsigned)(r * 128 + (((2 * ks + acs) ^ (r & 7)) << 4));
                asm volatile(
                    "ldmatrix.sync.aligned.m8n8.x4.shared.b16 {%0,%1,%2,%3}, [%4];"
                    : "=r"(a[mt][0]), "=r"(a[mt][1]), "=r"(a[mt][2]), "=r"(a[mt][3])
                    : "r"(ad));
            }
#pragma unroll
            for (int nt = 0; nt < 4; nt++) {
                int r = brow + nt * 8;
                unsigned bd = sb + (unsigned)(ASZ * 4) +
                              (unsigned)(r * 128 + (((2 * ks + bcs) ^ (r & 7)) << 4));
                asm volatile(
                    "ldmatrix.sync.aligned.m8n8.x2.shared.b16 {%0,%1}, [%2];"
                    : "=r"(bf[nt][0]), "=r"(bf[nt][1])
                    : "r"(bd));
            }
#pragma unroll
            for (int mt = 0; mt < 4; mt++)
#pragma unroll
                for (int nt = 0; nt < 4; nt++)
                    asm volatile(
                        "mma.sync.aligned.m16n8k16.row.col.f32.f16.f16.f32 "
                        "{%0,%1,%2,%3}, {%4,%5,%6,%7}, {%8,%9}, {%0,%1,%2,%3};"
                        : "+f"(acc[mt][nt][0]), "+f"(acc[mt][nt][1]),
                          "+f"(acc[mt][nt][2]), "+f"(acc[mt][nt][3])
                        : "r"(a[mt][0]), "r"(a[mt][1]), "r"(a[mt][2]), "r"(a[mt][3]),
                          "r"(bf[nt][0]), "r"(bf[nt][1]));
        }
    }

    const int gg = lane >> 2, tt = lane & 3;
    if (!SPLIT) {
#pragma unroll
        for (int mt = 0; mt < 4; mt++) {
            int r = row0 + wm * 64 + mt * 16 + gg;
#pragma unroll
            for (int nt = 0; nt < 4; nt++) {
                int cc = col0 + wn * 32 + nt * 8 + 2 * tt;
                *(float2*)&Cz[(size_t)r * N + cc]       = make_float2(acc[mt][nt][0], acc[mt][nt][1]);
                *(float2*)&Cz[(size_t)(r + 8) * N + cc] = make_float2(acc[mt][nt][2], acc[mt][nt][3]);
            }
        }
    } else if (col0 < DMODEL) {
#pragma unroll
        for (int mt = 0; mt < 4; mt++) {
            int r = row0 + wm * 64 + mt * 16 + gg;
#pragma unroll
            for (int nt = 0; nt < 4; nt++) {
                int cc = col0 + wn * 32 + nt * 8 + 2 * tt;
                *(float2*)&Cz[(size_t)r * DMODEL + cc]       = make_float2(acc[mt][nt][0], acc[mt][nt][1]);
                *(float2*)&Cz[(size_t)(r + 8) * DMODEL + cc] = make_float2(acc[mt][nt][2], acc[mt][nt][3]);
            }
        }
    } else {
#pragma unroll
        for (int mt = 0; mt < 4; mt++) {
            int r = row0 + wm * 64 + mt * 16 + gg;
#pragma unroll
            for (int nt = 0; nt < 4; nt++) {
                int cc = col0 - DMODEL + wn * 32 + nt * 8 + 2 * tt;
                __half2 h0 = __floats2half2_rn(acc[mt][nt][0], acc[mt][nt][1]);
                __half2 h1 = __floats2half2_rn(acc[mt][nt][2], acc[mt][nt][3]);
                *(__half2*)&Ch[(size_t)r * CONVD + cc]       = h0;
                *(__half2*)&Ch[(size_t)(r + 8) * CONVD + cc] = h1;
            }
        }
    }
}

// ============================================================================
// Fused conv+SiLU+SSD, all-tensor-core version.
// conv emits swizzled fp16 tiles X/B/C; G = (C.B^T).*causal via MMA with
// fp16 G written back swizzled; Y = G.X via MMA (X through ldmatrix.trans),
// fp32 accum, direct fp16 global store. Chunk state from fp16 tiles.
// smem bytes: XsH@0 BsH@8K CsH@16K GsH@24K staging@32K(28512) = 61280.
// ============================================================================
#define HST  72                            // staging stride in halves
#define RSTG (66 * HST * 2)                // 9504 B per region
#define XSH_OFF   0
#define BSH_OFF   8192
#define CSH_OFF   16384
#define GSH_OFF   24576
#define STAGE_OFF 32768
#define SSD_SMEM  (STAGE_OFF + 3 * RSTG)   // 61280

__global__ __launch_bounds__(256, 2) void ssd_chunk_kernel(
    const __half* __restrict__ xbch, const float* __restrict__ cw,
    const float* __restrict__ cb,    __half* __restrict__ chx,
    __half* __restrict__ ydiag,      float* __restrict__ cs)
{
    extern __shared__ __align__(16) char smc[];
    char* XsH = smc + XSH_OFF;
    char* BsH = smc + BSH_OFF;
    char* CsH = smc + CSH_OFF;
    char* GsH = smc + GSH_OFF;
    char* Hs  = smc + STAGE_OFF;

    int bid = blockIdx.x;
    int c  = bid & 63;
    int bh = bid >> 6;
    int h  = bh & 31;
    int b  = bh >> 5;
    int sl0 = c * CHUNK;
    size_t rbase = (size_t)b * SEQ + sl0;
    int tid = threadIdx.x;
    const int wid = tid >> 5, lane = tid & 31;

    // ---- stage 3 regions x 66 rows (halo +-1) into smem ----
    for (int i = tid; i < 3 * 66 * 8; i += 256) {
        int reg = i / 528;
        int rem = i - reg * 528;
        int row = rem >> 3;
        int ch  = rem & 7;
        int sl  = sl0 - 1 + row;
        char* dst = Hs + reg * RSTG + row * (HST * 2) + ch * 16;
        if (sl >= 0 && sl < SEQ) {
            cp16(dst, xbch + ((size_t)b * SEQ + sl) * CONVD + reg * 2048 + h * 64 + ch * 8);
        } else {
            sts_zero16(dst);
        }
    }
    asm volatile("cp.async.commit_group;");
    asm volatile("cp.async.wait_group 0;");
    __syncthreads();

    // ---- conv + silu -> swizzled fp16 tiles ----
#pragma unroll
    for (int reg = 0; reg < 3; reg++) {
        const char* Hreg = Hs + reg * RSTG;
        char* dstH = (reg == 0) ? XsH : (reg == 1) ? BsH : CsH;
        int chbase = reg * 2048 + h * 64;
        for (int i = tid; i < 64 * 16; i += 256) {
            int l = i >> 4, q = (i & 15) * 4;
            size_t r = rbase + l;
            const char* rp = Hreg + l * (HST * 2) + q * 2;
            uint2 um = *(const uint2*)(rp);
            uint2 u0 = *(const uint2*)(rp + HST * 2);
            uint2 up = *(const uint2*)(rp + HST * 4);
            __half2 h0a = *(__half2*)&u0.x, h0b = *(__half2*)&u0.y;
            __half2 hma = *(__half2*)&um.x, hmb = *(__half2*)&um.y;
            __half2 hpa = *(__half2*)&up.x, hpb = *(__half2*)&up.y;
            float4 x0 = make_float4(__low2float(h0a), __high2float(h0a),
                                    __low2float(h0b), __high2float(h0b));
            float4 xm = make_float4(__low2float(hma), __high2float(hma),
                                    __low2float(hmb), __high2float(hmb));
            float4 xp = make_float4(__low2float(hpa), __high2float(hpa),
                                    __low2float(hpb), __high2float(hpb));
            int ch = chbase + q;
            float4 v;
            v.x = fmaf(cw[3*ch+0], xm.x, fmaf(cw[3*ch+1], x0.x, fmaf(cw[3*ch+2], xp.x, cb[ch])));
            v.y = fmaf(cw[3*ch+3], xm.y, fmaf(cw[3*ch+4], x0.y, fmaf(cw[3*ch+5], xp.y, cb[ch+1])));
            v.z = fmaf(cw[3*ch+6], xm.z, fmaf(cw[3*ch+7], x0.z, fmaf(cw[3*ch+8], xp.z, cb[ch+2])));
            v.w = fmaf(cw[3*ch+9], xm.w, fmaf(cw[3*ch+10], x0.w, fmaf(cw[3*ch+11], xp.w, cb[ch+3])));
            v.x = silu(v.x); v.y = silu(v.y); v.z = silu(v.z); v.w = silu(v.w);

            __half2 lo = __floats2half2_rn(v.x, v.y);
            __half2 hi = __floats2half2_rn(v.z, v.w);
            uint2 hv;
            hv.x = *(unsigned*)&lo;
            hv.y = *(unsigned*)&hi;
            int addr = l * 128 + (((q >> 3) ^ (l & 7)) << 4) + ((q & 4) << 1);
            *(uint2*)(dstH + addr) = hv;
            if (reg == 2)
                *(uint2*)&chx[r * DMODEL + h * 64 + q] = hv;
        }
    }
    __syncthreads();

    const unsigned xBase = (unsigned)__cvta_generic_to_shared(XsH);
    const unsigned bBase = (unsigned)__cvta_generic_to_shared(BsH);
    const unsigned cBase = (unsigned)__cvta_generic_to_shared(CsH);
    const unsigned gBase = (unsigned)__cvta_generic_to_shared(GsH);

    const int wrow = (wid & 3) * 16;       // warp's 16-row stripe
    const int wcol = (wid >> 2) * 32;      // warp's 32-col half
    const int g  = lane >> 2, t4 = lane & 3;

    // ---- G = C . B^T via MMA; causal mask; store fp16 swizzled GsH ----
    {
        const int ar = wrow + (lane & 15);
        const int acsl = lane >> 4;
        const int br0 = wcol + (lane & 7);
        const int bcsl = (lane >> 3) & 1;

        float acc[4][4];
#pragma unroll
        for (int i = 0; i < 4; i++)
#pragma unroll
            for (int j = 0; j < 4; j++) acc[i][j] = 0.f;

#pragma unroll
        for (int ks = 0; ks < 4; ks++) {
            unsigned a[4];
            unsigned ad = cBase + (unsigned)(ar * 128 + (((2 * ks + acsl) ^ (ar & 7)) << 4));
            asm volatile(
                "ldmatrix.sync.aligned.m8n8.x4.shared.b16 {%0,%1,%2,%3}, [%4];"
                : "=r"(a[0]), "=r"(a[1]), "=r"(a[2]), "=r"(a[3]) : "r"(ad));
#pragma unroll
            for (int nt = 0; nt < 4; nt++) {
                int rr = br0 + nt * 8;
                unsigned bd = bBase + (unsigned)(rr * 128 + (((2 * ks + bcsl) ^ (rr & 7)) << 4));
                unsigned bf0, bf1;
                asm volatile(
                    "ldmatrix.sync.aligned.m8n8.x2.shared.b16 {%0,%1}, [%2];"
                    : "=r"(bf0), "=r"(bf1) : "r"(bd));
                asm volatile(
                    "mma.sync.aligned.m16n8k16.row.col.f32.f16.f16.f32 "
                    "{%0,%1,%2,%3}, {%4,%5,%6,%7}, {%8,%9}, {%0,%1,%2,%3};"
                    : "+f"(acc[nt][0]), "+f"(acc[nt][1]), "+f"(acc[nt][2]), "+f"(acc[nt][3])
                    : "r"(a[0]), "r"(a[1]), "r"(a[2]), "r"(a[3]), "r"(bf0), "r"(bf1));
            }
        }
        int r0 = wrow + g, r1 = r0 + 8;
#pragma unroll
        for (int nt = 0; nt < 4; nt++) {
            int c0 = wcol + nt * 8 + 2 * t4;
            float v00 = (r0 >= c0)     ? acc[nt][0] : 0.f;
            float v01 = (r0 >= c0 + 1) ? acc[nt][1] : 0.f;
            float v10 = (r1 >= c0)     ? acc[nt][2] : 0.f;
            float v11 = (r1 >= c0 + 1) ? acc[nt][3] : 0.f;
            __half2 h0 = __floats2half2_rn(v00, v01);
            __half2 h1 = __floats2half2_rn(v10, v11);
            int a0 = r0 * 128 + (((c0 >> 3) ^ (r0 & 7)) << 4) + 4 * t4;
            int a1 = r1 * 128 + (((c0 >> 3) ^ (r1 & 7)) << 4) + 4 * t4;
            *(__half2*)(GsH + a0) = h0;
            *(__half2*)(GsH + a1) = h1;
        }
    }
    __syncthreads();

    // ---- Y = G . X via MMA (A = GsH rows l, k=m; B = XsH via ldmatrix.trans) ----
    {
        const int ar = wrow + (lane & 15);
        const int acsl = lane >> 4;

        float acc[4][4];
#pragma unroll
        for (int i = 0; i < 4; i++)
#pragma unroll
            for (int j = 0; j < 4; j++) acc[i][j] = 0.f;

#pragma unroll
        for (int ks = 0; ks < 4; ks++) {
            unsigned a[4];
            unsigned ad = gBase + (unsigned)(ar * 128 + (((2 * ks + acsl) ^ (ar & 7)) << 4));
            asm volatile(
                "ldmatrix.sync.aligned.m8n8.x4.shared.b16 {%0,%1,%2,%3}, [%4];"
                : "=r"(a[0]), "=r"(a[1]), "=r"(a[2]), "=r"(a[3]) : "r"(ad));
            int brr = ks * 16 + (lane & 15);   // X row = k = m
#pragma unroll
            for (int nt = 0; nt < 4; nt++) {
                int n0 = wcol + nt * 8;
                unsigned bd = xBase + (unsigned)(brr * 128 + (((n0 >> 3) ^ (brr & 7)) << 4));
                unsigned bf0, bf1;
                asm volatile(
                    "ldmatrix.sync.aligned.m8n8.x2.trans.shared.b16 {%0,%1}, [%2];"
                    : "=r"(bf0), "=r"(bf1) : "r"(bd));
                asm volatile(
                    "mma.sync.aligned.m16n8k16.row.col.f32.f16.f16.f32 "
                    "{%0,%1,%2,%3}, {%4,%5,%6,%7}, {%8,%9}, {%0,%1,%2,%3};"
                    : "+f"(acc[nt][0]), "+f"(acc[nt][1]), "+f"(acc[nt][2]), "+f"(acc[nt][3])
                    : "r"(a[0]), "r"(a[1]), "r"(a[2]), "r"(a[3]), "r"(bf0), "r"(bf1));
            }
        }
        // epilogue: direct fp16 global store
        int r0 = wrow + g, r1 = r0 + 8;
        __half* y0 = &ydiag[(rbase + r0) * DMODEL + h * 64];
        __half* y1 = &ydiag[(rbase + r1) * DMODEL + h * 64];
#pragma unroll
        for (int nt = 0; nt < 4; nt++) {
            int c0 = wcol + nt * 8 + 2 * t4;
            *(__half2*)&y0[c0] = __floats2half2_rn(acc[nt][0], acc[nt][1]);
            *(__half2*)&y1[c0] = __floats2half2_rn(acc[nt][2], acc[nt][3]);
        }
    }

    // ---- chunk state from fp16 tiles (fp32 accumulate) ----
    if (tid < 64) {
        int n = tid;
        int chn = n >> 3, off = (n & 7) * 2;
        float a = 0.f;
#pragma unroll 8
        for (int l = 0; l < 64; l++) {
            int sw = l * 128 + ((chn ^ (l & 7)) << 4) + off;
            float xv = __half2float(*(const __half*)(XsH + sw));
            float bv = __half2float(*(const __half*)(BsH + sw));
            a = fmaf(xv, bv, a);
        }
        cs[(size_t)bid * 64 + n] = a;
    }
}

// ============================================================================
// Inter-chunk scan
// ============================================================================
__global__ void scan_kernel(const float* __restrict__ cs, const float* __restrict__ A_log,
                            float* __restrict__ prev)
{
    int bh = blockIdx.x;
    int h  = bh & 31;
    int n  = threadIdx.x;
    float d = __expf(63.f * A_log[h]);
    float s = 0.f;
    for (int c = 0; c < NCHUNK; c++) {
        size_t idx = ((size_t)bh * NCHUNK + c) * 64 + n;
        prev[idx] = s;
        s = s * d + cs[idx];
    }
}

// ============================================================================
// Y = Y_diag + Y_off; gate silu(z); RMSNorm. Vectorized.
// ============================================================================
__global__ __launch_bounds__(256) void combine_kernel(
    const __half* __restrict__ ydiag, const float* __restrict__ gz,
    const __half* __restrict__ chx,   const float* __restrict__ prev,
    const float* __restrict__ rms_w,  __half* __restrict__ yn)
{
    int r = blockIdx.x;
    int b = r >> 12;
    int l = r & (SEQ - 1);
    int c = l >> 6;

    __shared__ float sh_yoff[NHEADS];
    __shared__ float sh_red[8];

    int tid = threadIdx.x, warp = tid >> 5, lane = tid & 31;

    for (int h = warp; h < NHEADS; h += 8) {
        const __half* Crow = chx + (size_t)r * DMODEL + h * 64;
        const float* pv    = prev + ((size_t)(b * NHEADS + h) * NCHUNK + c) * 64;
        int n0 = lane * 2;
        float v = __half2float(Crow[n0]) * pv[n0] + __half2float(Crow[n0 + 1]) * pv[n0 + 1];
#pragma unroll
        for (int o = 16; o; o >>= 1) v += __shfl_down_sync(0xffffffffu, v, o);
        if (lane == 0) sh_yoff[h] = v;
    }
    __syncthreads();

    const int d0 = tid * 8;
    float4 z0 = *(const float4*)&gz[(size_t)r * DMODEL + d0];
    float4 z1 = *(const float4*)&gz[(size_t)r * DMODEL + d0 + 4];
    uint4 yd  = *(const uint4*)&ydiag[(size_t)r * DMODEL + d0];
    __half2 y01 = *(__half2*)&yd.x, y23 = *(__half2*)&yd.y;
    __half2 y45 = *(__half2*)&yd.z, y67 = *(__half2*)&yd.w;
    float yoff = sh_yoff[d0 >> 6];

    float vals[8];
    vals[0] = (__low2float(y01)  + yoff) * silu(z0.x);
    vals[1] = (__high2float(y01) + yoff) * silu(z0.y);
    vals[2] = (__low2float(y23)  + yoff) * silu(z0.z);
    vals[3] = (__high2float(y23) + yoff) * silu(z0.w);
    vals[4] = (__low2float(y45)  + yoff) * silu(z1.x);
    vals[5] = (__high2float(y45) + yoff) * silu(z1.y);
    vals[6] = (__low2float(y67)  + yoff) * silu(z1.z);
    vals[7] = (__high2float(y67) + yoff) * silu(z1.w);

    float ss = 0.f;
#pragma unroll
    for (int j = 0; j < 8; j++) ss += vals[j] * vals[j];
#pragma unroll
    for (int o = 16; o; o >>= 1) ss += __shfl_down_sync(0xffffffffu, ss, o);
    if (lane == 0) sh_red[warp] = ss;
    __syncthreads();
    if (tid == 0) {
        float t = 0.f;
#pragma unroll
        for (int w = 0; w < 8; w++) t += sh_red[w];
        sh_red[0] = rsqrtf(t / (float)DMODEL + RMS_EPS);
    }
    __syncthreads();
    float scale = sh_red[0];

    float4 rw0 = *(const float4*)&rms_w[d0];
    float4 rw1 = *(const float4*)&rms_w[d0 + 4];
    __half2 o0 = __floats2half2_rn(vals[0] * scale * rw0.x, vals[1] * scale * rw0.y);
    __half2 o1 = __floats2half2_rn(vals[2] * scale * rw0.z, vals[3] * scale * rw0.w);
    __half2 o2 = __floats2half2_rn(vals[4] * scale * rw1.x, vals[5] * scale * rw1.y);
    __half2 o3 = __floats2half2_rn(vals[6] * scale * rw1.z, vals[7] * scale * rw1.w);
    uint4 ov = make_uint4(*(unsigned*)&o0, *(unsigned*)&o1, *(unsigned*)&o2, *(unsigned*)&o3);
    *(uint4*)&yn[(size_t)r * DMODEL + d0] = ov;
}

// ============================================================================
// launch
// ============================================================================
extern "C" void kernel_launch(void* const* d_in, const int* in_sizes, int n_in,
                              void* d_out, int out_size)
{
    const float* u      = (const float*)d_in[0];
    const float* W_in   = (const float*)d_in[1];
    const float* W_out  = (const float*)d_in[2];
    const float* conv_w = (const float*)d_in[3];
    const float* conv_b = (const float*)d_in[4];
    const float* A_log  = (const float*)d_in[5];
    const float* rms_w  = (const float*)d_in[6];
    float* out = (float*)d_out;

    float *gz, *cs, *prev;
    __half *xbch, *chx, *y, *yn, *ut, *wit, *wot;
    cudaGetSymbolAddress((void**)&gz,   g_z);
    cudaGetSymbolAddress((void**)&xbch, g_xbch);
    cudaGetSymbolAddress((void**)&chx,  g_ch);
    cudaGetSymbolAddress((void**)&y,    g_y);
    cudaGetSymbolAddress((void**)&yn,   g_yn);
    cudaGetSymbolAddress((void**)&cs,   g_cs);
    cudaGetSymbolAddress((void**)&prev, g_prev);
    cudaGetSymbolAddress((void**)&ut,   g_ut);
    cudaGetSymbolAddress((void**)&wit,  g_wit);
    cudaGetSymbolAddress((void**)&wot,  g_wot);

    static bool attr_done = false;
    if (!attr_done) {
        cudaFuncSetAttribute(gemm_tn_f16<true>,  cudaFuncAttributeMaxDynamicSharedMemorySize, GSMEM);
        cudaFuncSetAttribute(gemm_tn_f16<false>, cudaFuncAttributeMaxDynamicSharedMemorySize, GSMEM);
        cudaFuncSetAttribute(ssd_chunk_kernel, cudaFuncAttributeMaxDynamicSharedMemorySize, SSD_SMEM);
        attr_done = true;
    }

    // 0) convert operands to fp16
    {
        size_t n4u = (size_t)ROWS * DMODEL / 4;
        h_convert<<<(unsigned)((n4u + 255) / 256), 256>>>(u, ut, n4u);
        size_t n4w = (size_t)ZXB_LD * DMODEL / 4;
        h_convert<<<(unsigned)((n4w + 255) / 256), 256>>>(W_in, wit, n4w);
        size_t n4o = (size_t)DMODEL * DMODEL / 4;
        h_convert<<<(unsigned)((n4o + 255) / 256), 256>>>(W_out, wot, n4o);
    }
    // 1) split GEMM1: z -> fp32 gz, xBC -> fp16 xbch
    gemm_tn_f16<true><<<dim3(ZXB_LD / 128, ROWS / 128), 256, GSMEM>>>(
        ut, wit, gz, xbch, ROWS, ZXB_LD, DMODEL);
    // 2) fused conv + silu + per-chunk SSD (all tensor-core)
    ssd_chunk_kernel<<<BATCH * NHEADS * NCHUNK, 256, SSD_SMEM>>>(xbch, conv_w, conv_b, chx, y, cs);
    // 3) inter-chunk scan
    scan_kernel<<<BATCH * NHEADS, 64>>>(cs, A_log, prev);
    // 4) Y_off + gate + rmsnorm
    combine_kernel<<<ROWS, 256>>>(y, gz, chx, prev, rms_w, yn);
    // 5) out = yn @ W_out^T (fp32 out)
    gemm_tn_f16<false><<<dim3(DMODEL / 128, ROWS / 128), 256, GSMEM>>>(
        yn, wot, out, (__half*)nullptr, ROWS, DMODEL, DMODEL);
}